// round 12
// baseline (speedup 1.0000x reference)
#include <cuda_runtime.h>
#include <cstdint>

// AttentionConvolution2D: B=2, DIN=128, H=W=256, BS=4, NH=8, DH=32, DOUT=128
typedef unsigned long long u64;

__device__ __forceinline__ uint32_t to_tf32(float f) {
    uint32_t r; asm("cvt.rna.tf32.f32 %0, %1;" : "=r"(r) : "f"(f)); return r;
}
__device__ __forceinline__ void mma_tf32(float* d,
                                         uint32_t a0, uint32_t a1, uint32_t a2, uint32_t a3,
                                         uint32_t b0, uint32_t b1) {
    asm("mma.sync.aligned.m16n8k8.row.col.f32.tf32.tf32.f32 "
        "{%0,%1,%2,%3}, {%4,%5,%6,%7}, {%8,%9}, {%0,%1,%2,%3};"
        : "+f"(d[0]), "+f"(d[1]), "+f"(d[2]), "+f"(d[3])
        : "r"(a0), "r"(a1), "r"(a2), "r"(a3), "r"(b0), "r"(b1));
}
__device__ __forceinline__ void cpa16(uint32_t dst, const void* src) {
    asm volatile("cp.async.cg.shared.global [%0], [%1], 16;" :: "r"(dst), "l"(src));
}
__device__ __forceinline__ void cp_commit() {
    asm volatile("cp.async.commit_group;");
}
template <int N> __device__ __forceinline__ void cp_wait() {
    asm volatile("cp.async.wait_group %0;" :: "n"(N));
}

// proj scratch, tile-major, TF32 BIT PATTERNS (q pre-scaled by 1/sqrt(32)):
// tile=(b*64+hb)*64+vb, row=pixel pi=(w&3)*4+(h&3), 768 ch/row (q|k|v)
__device__ float g_proj[100663296];     // 131072*768 words
__device__ uint32_t g_wfrag[98304];     // w_in  in m16n8k8 A-fragment order (tf32)
__device__ u64 g_wofrag[16384];         // w_out in m16n8k8 B-fragment order (tf32 pairs)

// ---------------- K1a: pack w_in (768x128) into A-fragment order -------------
__global__ void wfrag_kernel(const float* __restrict__ w_in) {
    int idx = blockIdx.x * 256 + threadIdx.x;     // 0..24575
    if (idx >= 24576) return;
    int lane = idx & 31, kk = (idx >> 5) & 15, mb = idx >> 9;
    int g = lane >> 2, q = lane & 3;
    int r0 = mb * 16 + g, r1 = r0 + 8;
    int c0 = kk * 8 + q,  c1 = c0 + 4;
    uint4 o;
    o.x = to_tf32(w_in[r0 * 128 + c0]);
    o.y = to_tf32(w_in[r1 * 128 + c0]);
    o.z = to_tf32(w_in[r0 * 128 + c1]);
    o.w = to_tf32(w_in[r1 * 128 + c1]);
    *(uint4*)&g_wfrag[idx * 4] = o;
}

// ---------------- K1b: pack w_out (128x256) into B-fragment order ------------
__global__ void wofrag_kernel(const float* __restrict__ w_out) {
    int f = blockIdx.x * 256 + threadIdx.x;       // 0..16383
    if (f >= 16384) return;
    int lane = f & 31, kc = (f >> 5) & 31, cb = f >> 10;
    int g = lane >> 2, q = lane & 3;
    int c = cb * 8 + g;
    uint32_t b0 = to_tf32(w_out[c * 256 + kc * 8 + q]);
    uint32_t b1 = to_tf32(w_out[c * 256 + kc * 8 + q + 4]);
    g_wofrag[f] = (u64)b0 | ((u64)b1 << 32);
}

// ---------------- K2: projection GEMM via tf32 MMA, 128 px per CTA -----------
// x strip (128 px x 128 k, tf32) in dynamic smem, stride 136 (conflict-free);
// weights streamed from L2 once per CTA -> half the weight traffic of 64px.
__global__ __launch_bounds__(256, 3) void proj_mma_kernel(const float* __restrict__ x,
                                                          const float* __restrict__ b_in) {
    extern __shared__ uint32_t sB[];      // [128][136] = 69632 B

    const int t   = threadIdx.x;
    const int pbk = blockIdx.x;           // 0..1023
    const int b   = pbk >> 9;
    const int rem = pbk & 511;
    const int hc  = rem >> 1;             // h 0..255
    const int w0  = (rem & 1) << 7;       // first w of 128-px strip

    const float* xb = x + ((size_t)b << 23) + (size_t)hc * 256 + w0;

#pragma unroll
    for (int r = 0; r < 16; ++r) {
        int flat = r * 1024 + t * 4;
        int k = flat >> 7, px = flat & 127;
        float4 v = *(const float4*)&xb[(size_t)k * 65536 + px];
        uint4 o = { to_tf32(v.x), to_tf32(v.y), to_tf32(v.z), to_tf32(v.w) };
        *(uint4*)&sB[k * 136 + px] = o;
    }
    __syncthreads();

    const int warp = t >> 5, lane = t & 31;
    const int wm = warp >> 1, wn = warp & 1;
    const int nw0 = wn << 6;              // 64-px half per wn
    const int g = lane >> 2, q = lane & 3;

    const int vbb = hc >> 2, py = hc & 3;
    const float SCALE = 0.17677669529663687f;   // 1/sqrt(32)

    for (int nbk = 0; nbk < 6; ++nbk) {
        const int mbase = nbk * 8 + wm * 2;
        const float sc = (nbk < 2) ? SCALE : 1.0f;
        float acc[2][8][4];
#pragma unroll
        for (int m = 0; m < 2; ++m)
#pragma unroll
            for (int nb = 0; nb < 8; ++nb)
#pragma unroll
                for (int e = 0; e < 4; ++e) acc[m][nb][e] = 0.0f;

#pragma unroll
        for (int kk = 0; kk < 16; ++kk) {
            uint4 a0 = *(const uint4*)&g_wfrag[(((mbase + 0) * 16 + kk) * 32 + lane) * 4];
            uint4 a1 = *(const uint4*)&g_wfrag[(((mbase + 1) * 16 + kk) * 32 + lane) * 4];
            const int rb0 = (kk * 8 + q) * 136 + nw0 + g;
#pragma unroll
            for (int nb = 0; nb < 8; ++nb) {
                uint32_t bf0 = sB[rb0 + nb * 8];
                uint32_t bf1 = sB[rb0 + 544 + nb * 8];   // +4 k-rows
                mma_tf32(acc[0][nb], a0.x, a0.y, a0.z, a0.w, bf0, bf1);
                mma_tf32(acc[1][nb], a1.x, a1.y, a1.z, a1.w, bf0, bf1);
            }
        }

        // epilogue: + bias, scatter to tile-major proj layout (tf32 bits)
#pragma unroll
        for (int nb = 0; nb < 8; ++nb) {
#pragma unroll
            for (int e = 0; e < 2; ++e) {
                int w  = w0 + nw0 + nb * 8 + 2 * q + e;
                int hb = w >> 2, pxm = w & 3;
                size_t base = ((((size_t)b * 64 + hb) * 64 + vbb) * 16 + pxm * 4 + py) * 768;
#pragma unroll
                for (int m = 0; m < 2; ++m) {
                    int ch0 = nbk * 128 + (wm * 2 + m) * 16 + g;
                    float bias0 = b_in[ch0];
                    float bias1 = b_in[ch0 + 8];
                    g_proj[base + ch0]     = __uint_as_float(to_tf32((acc[m][nb][e] + bias0) * sc));
                    g_proj[base + ch0 + 8] = __uint_as_float(to_tf32((acc[m][nb][e + 2] + bias1) * sc));
                }
            }
        }
    }
}

// ---------------- K3: attention, all-MMA, double-buffered cp.async -----------
// (unchanged from R10 best: 657 us config)
#define STAGE_WORDS 8512

__global__ __launch_bounds__(256, 3) void attn_mma_kernel(const float* __restrict__ b_out,
                                                          float* __restrict__ out) {
    extern __shared__ uint32_t usm[];

    const int bid = blockIdx.x;
    const int vb = bid & 63;
    const int hb = (bid >> 6) & 63;
    const int b  = bid >> 12;
    const int t  = threadIdx.x;
    const int warp = t >> 5, lane = t & 31;
    const int h = warp;
    const int g = lane >> 2, q = lane & 3;

    const uint32_t* tbu = (const uint32_t*)g_proj + (size_t)bid * 12288;

    uint32_t qa0[4], qa1[4], qa2[4], qa3[4];
#pragma unroll
    for (int kc = 0; kc < 4; ++kc) {
        int base = (h << 5) + kc * 8 + q;
        qa0[kc] = tbu[g * 768 + base];
        qa1[kc] = tbu[(g + 8) * 768 + base];
        qa2[kc] = tbu[g * 768 + base + 4];
        qa3[kc] = tbu[(g + 8) * 768 + base + 4];
    }

    int nidx[9], ndxy[9], n = 0;
    for (int dx = 0; dx < 3; ++dx) {
        int nhb = hb + dx - 1;
        if ((unsigned)nhb >= 64u) continue;      // boundary == -inf mask
        for (int dy = 0; dy < 3; ++dy) {
            int nvb = vb + dy - 1;
            if ((unsigned)nvb >= 64u) continue;
            nidx[n] = (b << 12) + (nhb << 6) + nvb;
            ndxy[n] = (dx << 4) | dy;
            ++n;
        }
    }

    const uint32_t aS = (uint32_t)__cvta_generic_to_shared(usm);

    auto fill = [&](int i, int sp) {
        const float* nb_ = g_proj + (size_t)nidx[i] * 12288 + 256;
        uint32_t bs = aS + sp * (STAGE_WORDS * 4);
#pragma unroll
        for (int r = 0; r < 4; ++r) {
            int flat = r * 1024 + t * 4;
            int key = flat >> 8, ch = flat & 255;
            cpa16(bs + (key * 268 + ch) * 4, nb_ + key * 768 + ch);
            cpa16(bs + (4288 + key * 264 + ch) * 4, nb_ + key * 768 + 256 + ch);
        }
        cp_commit();
    };

    float oacc[4][4];
#pragma unroll
    for (int nb = 0; nb < 4; ++nb)
#pragma unroll
        for (int e = 0; e < 4; ++e) oacc[nb][e] = 0.0f;
    float m_g = -1e30f, m_g8 = -1e30f, l_g = 0.0f, l_g8 = 0.0f;

    const int qx_g  = g >> 2,       qy_g  = g & 3;
    const int qx_g8 = (g + 8) >> 2, qy_g8 = (g + 8) & 3;
    const int srcA = (lane & 0x1c) | (q >> 1);
    const int srcC = srcA + 2;

    fill(0, 0);
    if (n > 1) fill(1, 1);

    for (int i = 0; i < n; ++i) {
        const int sp = i & 1;
        if (i + 1 < n) cp_wait<1>(); else cp_wait<0>();
        __syncthreads();

        const uint32_t* uK = usm + sp * STAGE_WORDS;
        const uint32_t* uV = uK + 4288;
        const int dx = ndxy[i] >> 4, dy = ndxy[i] & 15;

        float sacc[2][4];
#pragma unroll
        for (int nb = 0; nb < 2; ++nb)
#pragma unroll
            for (int e = 0; e < 4; ++e) sacc[nb][e] = 0.0f;
#pragma unroll
        for (int kc = 0; kc < 4; ++kc) {
#pragma unroll
            for (int nb = 0; nb < 2; ++nb) {
                uint32_t b0 = uK[(nb * 8 + g) * 268 + (h << 5) + kc * 8 + q];
                uint32_t b1 = uK[(nb * 8 + g) * 268 + (h << 5) + kc * 8 + q + 4];
                mma_tf32(sacc[nb], qa0[kc], qa1[kc], qa2[kc], qa3[kc], b0, b1);
            }
        }

#pragma unroll
        for (int nb = 0; nb < 2; ++nb)
#pragma unroll
            for (int e = 0; e < 2; ++e) {
                int j = nb * 8 + 2 * q + e, jx = j >> 2, jy = j & 3;
                int ixg = 4 * dx + jx - qx_g - 4,  iyg = 4 * dy + jy - qy_g - 4;
                int ixh = 4 * dx + jx - qx_g8 - 4, iyh = 4 * dy + jy - qy_g8 - 4;
                sacc[nb][e]     -= (float)(ixg * ixg + iyg * iyg) * 0.0625f;
                sacc[nb][e + 2] -= (float)(ixh * ixh + iyh * iyh) * 0.0625f;
            }

        float ml_g  = fmaxf(fmaxf(sacc[0][0], sacc[0][1]), fmaxf(sacc[1][0], sacc[1][1]));
        float ml_g8 = fmaxf(fmaxf(sacc[0][2], sacc[0][3]), fmaxf(sacc[1][2], sacc[1][3]));
        ml_g  = fmaxf(ml_g,  __shfl_xor_sync(0xffffffffu, ml_g, 1));
        ml_g  = fmaxf(ml_g,  __shfl_xor_sync(0xffffffffu, ml_g, 2));
        ml_g8 = fmaxf(ml_g8, __shfl_xor_sync(0xffffffffu, ml_g8, 1));
        ml_g8 = fmaxf(ml_g8, __shfl_xor_sync(0xffffffffu, ml_g8, 2));
        float mn_g  = fmaxf(m_g, ml_g),   cor_g  = __expf(m_g - mn_g);
        float mn_g8 = fmaxf(m_g8, ml_g8), cor_g8 = __expf(m_g8 - mn_g8);
        m_g = mn_g; m_g8 = mn_g8;

        float pp[2][4];
        float ls_g = 0.0f, ls_g8 = 0.0f;
#pragma unroll
        for (int nb = 0; nb < 2; ++nb) {
            pp[nb][0] = __expf(sacc[nb][0] - mn_g);
            pp[nb][1] = __expf(sacc[nb][1] - mn_g);
            pp[nb][2] = __expf(sacc[nb][2] - mn_g8);
            pp[nb][3] = __expf(sacc[nb][3] - mn_g8);
            ls_g  += pp[nb][0] + pp[nb][1];
            ls_g8 += pp[nb][2] + pp[nb][3];
        }
        ls_g  += __shfl_xor_sync(0xffffffffu, ls_g, 1);
        ls_g  += __shfl_xor_sync(0xffffffffu, ls_g, 2);
        ls_g8 += __shfl_xor_sync(0xffffffffu, ls_g8, 1);
        ls_g8 += __shfl_xor_sync(0xffffffffu, ls_g8, 2);
        l_g  = l_g  * cor_g  + ls_g;
        l_g8 = l_g8 * cor_g8 + ls_g8;

#pragma unroll
        for (int nb = 0; nb < 4; ++nb) {
            oacc[nb][0] *= cor_g;  oacc[nb][1] *= cor_g;
            oacc[nb][2] *= cor_g8; oacc[nb][3] *= cor_g8;
        }

        uint32_t pt[2][4];
#pragma unroll
        for (int nb = 0; nb < 2; ++nb)
#pragma unroll
            for (int e = 0; e < 4; ++e) pt[nb][e] = to_tf32(pp[nb][e]);

#pragma unroll
        for (int kc = 0; kc < 2; ++kc) {
            uint32_t v0 = __shfl_sync(0xffffffffu, pt[kc][0], srcA);
            uint32_t v1 = __shfl_sync(0xffffffffu, pt[kc][1], srcA);
            uint32_t w0 = __shfl_sync(0xffffffffu, pt[kc][2], srcA);
            uint32_t w1 = __shfl_sync(0xffffffffu, pt[kc][3], srcA);
            uint32_t x0 = __shfl_sync(0xffffffffu, pt[kc][0], srcC);
            uint32_t x1 = __shfl_sync(0xffffffffu, pt[kc][1], srcC);
            uint32_t y0 = __shfl_sync(0xffffffffu, pt[kc][2], srcC);
            uint32_t y1 = __shfl_sync(0xffffffffu, pt[kc][3], srcC);
            uint32_t a0 = (q & 1) ? v1 : v0;
            uint32_t a1 = (q & 1) ? w1 : w0;
            uint32_t a2 = (q & 1) ? x1 : x0;
            uint32_t a3 = (q & 1) ? y1 : y0;
#pragma unroll
            for (int nbd = 0; nbd < 4; ++nbd) {
                uint32_t b0 = uV[(kc * 8 + q) * 264 + (h << 5) + nbd * 8 + g];
                uint32_t b1 = uV[(kc * 8 + q + 4) * 264 + (h << 5) + nbd * 8 + g];
                mma_tf32(oacc[nbd], a0, a1, a2, a3, b0, b1);
            }
        }

        __syncthreads();
        if (i + 2 < n) fill(i + 2, sp);
    }

    uint32_t* uO = usm;   // stride 260
    {
        float inv_g = 1.0f / l_g, inv_g8 = 1.0f / l_g8;
#pragma unroll
        for (int nbd = 0; nbd < 4; ++nbd) {
            int c0 = (h << 5) + nbd * 8 + 2 * q;
            uO[g * 260 + c0]           = to_tf32(oacc[nbd][0] * inv_g);
            uO[g * 260 + c0 + 1]       = to_tf32(oacc[nbd][1] * inv_g);
            uO[(g + 8) * 260 + c0]     = to_tf32(oacc[nbd][2] * inv_g8);
            uO[(g + 8) * 260 + c0 + 1] = to_tf32(oacc[nbd][3] * inv_g8);
        }
    }
    __syncthreads();

    float cacc[2][4];
#pragma unroll
    for (int cb = 0; cb < 2; ++cb)
#pragma unroll
        for (int e = 0; e < 4; ++e) cacc[cb][e] = 0.0f;

#pragma unroll 8
    for (int kc = 0; kc < 32; ++kc) {
        uint32_t a0 = uO[g * 260 + kc * 8 + q];
        uint32_t a1 = uO[(g + 8) * 260 + kc * 8 + q];
        uint32_t a2 = uO[g * 260 + kc * 8 + q + 4];
        uint32_t a3 = uO[(g + 8) * 260 + kc * 8 + q + 4];
#pragma unroll
        for (int cbi = 0; cbi < 2; ++cbi) {
            u64 w2 = g_wofrag[(((warp * 2 + cbi) << 5) + kc) * 32 + lane];
            mma_tf32(cacc[cbi], a0, a1, a2, a3,
                     (uint32_t)(w2 & 0xffffffffu), (uint32_t)(w2 >> 32));
        }
    }

    const size_t ob = ((size_t)b << 23) + (size_t)(vb * 4) * 256 + hb * 4;
    const int pxg = g >> 2, pyg = g & 3;
    const int pxg8 = (g + 8) >> 2, pyg8 = (g + 8) & 3;
#pragma unroll
    for (int cbi = 0; cbi < 2; ++cbi) {
#pragma unroll
        for (int e = 0; e < 2; ++e) {
            int c = (warp * 2 + cbi) * 8 + 2 * q + e;
            float bo = __ldg(&b_out[c]);
            out[ob + (size_t)c * 65536 + pyg * 256 + pxg]   = cacc[cbi][e] + bo;
            out[ob + (size_t)c * 65536 + pyg8 * 256 + pxg8] = cacc[cbi][e + 2] + bo;
        }
    }
}

// ---------------------------------------------------------------------------
extern "C" void kernel_launch(void* const* d_in, const int* in_sizes, int n_in,
                              void* d_out, int out_size) {
    (void)in_sizes; (void)n_in; (void)out_size;
    const float* x     = (const float*)d_in[0];
    const float* w_in  = (const float*)d_in[1];
    const float* b_in  = (const float*)d_in[2];
    const float* w_out = (const float*)d_in[3];
    const float* b_out = (const float*)d_in[4];
    float* out = (float*)d_out;

    static int configured = 0;
    if (!configured) {
        cudaFuncSetAttribute(attn_mma_kernel, cudaFuncAttributeMaxDynamicSharedMemorySize, 69632);
        cudaFuncSetAttribute(proj_mma_kernel, cudaFuncAttributeMaxDynamicSharedMemorySize, 70656);
        configured = 1;
    }

    wfrag_kernel<<<96, 256>>>(w_in);
    wofrag_kernel<<<64, 256>>>(w_out);
    proj_mma_kernel<<<1024, 256, 69632>>>(x, b_in);
    attn_mma_kernel<<<8192, 256, 68096>>>(b_out, out);
}

// round 13
// speedup vs baseline: 1.8360x; 1.8360x over previous
#include <cuda_runtime.h>
#include <cstdint>

// AttentionConvolution2D: B=2, DIN=128, H=W=256, BS=4, NH=8, DH=32, DOUT=128
typedef unsigned long long u64;

__device__ __forceinline__ uint32_t to_tf32(float f) {
    uint32_t r; asm("cvt.rna.tf32.f32 %0, %1;" : "=r"(r) : "f"(f)); return r;
}
__device__ __forceinline__ void mma_tf32(float* d,
                                         uint32_t a0, uint32_t a1, uint32_t a2, uint32_t a3,
                                         uint32_t b0, uint32_t b1) {
    asm("mma.sync.aligned.m16n8k8.row.col.f32.tf32.tf32.f32 "
        "{%0,%1,%2,%3}, {%4,%5,%6,%7}, {%8,%9}, {%0,%1,%2,%3};"
        : "+f"(d[0]), "+f"(d[1]), "+f"(d[2]), "+f"(d[3])
        : "r"(a0), "r"(a1), "r"(a2), "r"(a3), "r"(b0), "r"(b1));
}
__device__ __forceinline__ void cpa16(uint32_t dst, const void* src) {
    asm volatile("cp.async.cg.shared.global [%0], [%1], 16;" :: "r"(dst), "l"(src));
}
__device__ __forceinline__ void cp_commit() {
    asm volatile("cp.async.commit_group;");
}
template <int N> __device__ __forceinline__ void cp_wait() {
    asm volatile("cp.async.wait_group %0;" :: "n"(N));
}

// proj scratch, tile-major, TF32 BIT PATTERNS (q pre-scaled by 1/sqrt(32)):
// tile=(b*64+hb)*64+vb, row=pixel pi=(w&3)*4+(h&3), 768 ch/row (q|k|v)
__device__ float g_proj[100663296];     // 131072*768 words
__device__ uint32_t g_wfrag[98304];     // w_in  in m16n8k8 A-fragment order (tf32)
__device__ u64 g_wofrag[16384];         // w_out in m16n8k8 B-fragment order (tf32 pairs)

// ---------------- K1a: pack w_in (768x128) into A-fragment order -------------
__global__ void wfrag_kernel(const float* __restrict__ w_in) {
    int idx = blockIdx.x * 256 + threadIdx.x;     // 0..24575
    if (idx >= 24576) return;
    int lane = idx & 31, kk = (idx >> 5) & 15, mb = idx >> 9;
    int g = lane >> 2, q = lane & 3;
    int r0 = mb * 16 + g, r1 = r0 + 8;
    int c0 = kk * 8 + q,  c1 = c0 + 4;
    uint4 o;
    o.x = to_tf32(w_in[r0 * 128 + c0]);
    o.y = to_tf32(w_in[r1 * 128 + c0]);
    o.z = to_tf32(w_in[r0 * 128 + c1]);
    o.w = to_tf32(w_in[r1 * 128 + c1]);
    *(uint4*)&g_wfrag[idx * 4] = o;
}

// ---------------- K1b: pack w_out (128x256) into B-fragment order ------------
__global__ void wofrag_kernel(const float* __restrict__ w_out) {
    int f = blockIdx.x * 256 + threadIdx.x;       // 0..16383
    if (f >= 16384) return;
    int lane = f & 31, kc = (f >> 5) & 31, cb = f >> 10;
    int g = lane >> 2, q = lane & 3;
    int c = cb * 8 + g;
    uint32_t b0 = to_tf32(w_out[c * 256 + kc * 8 + q]);
    uint32_t b1 = to_tf32(w_out[c * 256 + kc * 8 + q + 4]);
    g_wofrag[f] = (u64)b0 | ((u64)b1 << 32);
}

// ---------------- K2: projection GEMM via tf32 MMA (R9 64px, known-good) -----
__global__ __launch_bounds__(256) void proj_mma_kernel(const float* __restrict__ x,
                                                       const float* __restrict__ b_in) {
    __shared__ uint32_t sB[128 * 72];   // 36864 B

    const int t   = threadIdx.x;
    const int pbk = blockIdx.x;           // 0..2047
    const int b   = pbk >> 10;
    const int rem = pbk & 1023;
    const int hc  = rem >> 2;             // h 0..255
    const int w0  = (rem & 3) << 6;       // first w of strip

    const float* xb = x + ((size_t)b << 23) + (size_t)hc * 256 + w0;

#pragma unroll
    for (int r = 0; r < 8; ++r) {
        int flat = r * 1024 + t * 4;
        int k = flat >> 6, px = flat & 63;
        float4 v = *(const float4*)&xb[(size_t)k * 65536 + px];
        uint4 o = { to_tf32(v.x), to_tf32(v.y), to_tf32(v.z), to_tf32(v.w) };
        *(uint4*)&sB[k * 72 + px] = o;
    }
    __syncthreads();

    const int warp = t >> 5, lane = t & 31;
    const int wm = warp >> 1, wn = warp & 1;
    const int nw0 = wn << 5;
    const int g = lane >> 2, q = lane & 3;

    const int vbb = hc >> 2, py = hc & 3;
    size_t pxbase[4][2];
#pragma unroll
    for (int nb = 0; nb < 4; ++nb)
#pragma unroll
        for (int e = 0; e < 2; ++e) {
            int i  = nw0 + nb * 8 + 2 * q + e;
            int w  = w0 + i;
            int hb = w >> 2, pxm = w & 3;
            pxbase[nb][e] = ((((size_t)b * 64 + hb) * 64 + vbb) * 16 + pxm * 4 + py) * 768;
        }

    const float SCALE = 0.17677669529663687f;   // 1/sqrt(32)

    for (int nbk = 0; nbk < 6; ++nbk) {
        const int mbase = nbk * 8 + wm * 2;
        const float sc = (nbk < 2) ? SCALE : 1.0f;
        float acc[2][4][4];
#pragma unroll
        for (int m = 0; m < 2; ++m)
#pragma unroll
            for (int nb = 0; nb < 4; ++nb)
#pragma unroll
                for (int e = 0; e < 4; ++e) acc[m][nb][e] = 0.0f;

#pragma unroll
        for (int kk = 0; kk < 16; ++kk) {
            uint4 a0 = *(const uint4*)&g_wfrag[(((mbase + 0) * 16 + kk) * 32 + lane) * 4];
            uint4 a1 = *(const uint4*)&g_wfrag[(((mbase + 1) * 16 + kk) * 32 + lane) * 4];
            const int rb0 = (kk * 8 + q) * 72 + nw0 + g;
#pragma unroll
            for (int nb = 0; nb < 4; ++nb) {
                uint32_t bf0 = sB[rb0 + nb * 8];
                uint32_t bf1 = sB[rb0 + 288 + nb * 8];
                mma_tf32(acc[0][nb], a0.x, a0.y, a0.z, a0.w, bf0, bf1);
                mma_tf32(acc[1][nb], a1.x, a1.y, a1.z, a1.w, bf0, bf1);
            }
        }

#pragma unroll
        for (int m = 0; m < 2; ++m) {
            int ch0 = nbk * 128 + (wm * 2 + m) * 16 + g;
            float bias0 = b_in[ch0];
            float bias1 = b_in[ch0 + 8];
#pragma unroll
            for (int nb = 0; nb < 4; ++nb) {
                g_proj[pxbase[nb][0] + ch0]     = __uint_as_float(to_tf32((acc[m][nb][0] + bias0) * sc));
                g_proj[pxbase[nb][1] + ch0]     = __uint_as_float(to_tf32((acc[m][nb][1] + bias0) * sc));
                g_proj[pxbase[nb][0] + ch0 + 8] = __uint_as_float(to_tf32((acc[m][nb][2] + bias1) * sc));
                g_proj[pxbase[nb][1] + ch0 + 8] = __uint_as_float(to_tf32((acc[m][nb][3] + bias1) * sc));
            }
        }
    }
}

// ---------------- K3: attention — per-warp decoupled staging -----------------
// 256 threads = 8 warps, warp = head. Each warp stages ONLY its head's 32-ch
// slice of K and V: region (warp*2+stage)*1152 words, K[16key][36] then
// V[16key][36]. Total 18432 words = 73728 B -> 3 CTAs/SM.
// NO __syncthreads in the mainloop: fill/wait are warp-local.
__global__ __launch_bounds__(256, 3) void attn_mma_kernel(const float* __restrict__ b_out,
                                                          float* __restrict__ out) {
    extern __shared__ uint32_t usm[];

    const int bid = blockIdx.x;
    const int vb = bid & 63;
    const int hb = (bid >> 6) & 63;
    const int b  = bid >> 12;
    const int t  = threadIdx.x;
    const int warp = t >> 5, lane = t & 31;
    const int h = warp;
    const int g = lane >> 2, q = lane & 3;

    const uint32_t* tbu = (const uint32_t*)g_proj + (size_t)bid * 12288;

    // ---- Q fragments straight into registers (tf32 bits, pre-scaled) ----
    uint32_t qa0[4], qa1[4], qa2[4], qa3[4];
#pragma unroll
    for (int kc = 0; kc < 4; ++kc) {
        int base = (h << 5) + kc * 8 + q;
        qa0[kc] = tbu[g * 768 + base];
        qa1[kc] = tbu[(g + 8) * 768 + base];
        qa2[kc] = tbu[g * 768 + base + 4];
        qa3[kc] = tbu[(g + 8) * 768 + base + 4];
    }

    // ---- valid neighbor list (same for all warps) ----
    int nidx[9], ndxy[9], n = 0;
    for (int dx = 0; dx < 3; ++dx) {
        int nhb = hb + dx - 1;
        if ((unsigned)nhb >= 64u) continue;      // boundary == -inf mask
        for (int dy = 0; dy < 3; ++dy) {
            int nvb = vb + dy - 1;
            if ((unsigned)nvb >= 64u) continue;
            nidx[n] = (b << 12) + (nhb << 6) + nvb;
            ndxy[n] = (dx << 4) | dy;
            ++n;
        }
    }

    const uint32_t aS = (uint32_t)__cvta_generic_to_shared(usm);
    const int keyA   = lane >> 1;          // 0..15
    const int half16 = (lane & 1) * 16;    // word offset within 32-ch row

    // per-warp fill of stage sp for neighbor i (8 cpa16 per lane)
    auto fill = [&](int i, int sp) {
        const float* srcK = g_proj + (size_t)nidx[i] * 12288 + 256
                          + keyA * 768 + (h << 5);
        const uint32_t bs = aS + ((warp * 2 + sp) * 1152) * 4;
        const uint32_t dK = bs + (keyA * 36 + half16) * 4;
#pragma unroll
        for (int it = 0; it < 4; ++it) {
            cpa16(dK + it * 16,       srcK + half16 + it * 4);
            cpa16(dK + 2304 + it * 16, srcK + 256 + half16 + it * 4);
        }
        cp_commit();
    };

    float oacc[4][4];
#pragma unroll
    for (int nb = 0; nb < 4; ++nb)
#pragma unroll
        for (int e = 0; e < 4; ++e) oacc[nb][e] = 0.0f;
    float m_g = -1e30f, m_g8 = -1e30f, l_g = 0.0f, l_g8 = 0.0f;

    const int qx_g  = g >> 2,       qy_g  = g & 3;
    const int qx_g8 = (g + 8) >> 2, qy_g8 = (g + 8) & 3;
    const int srcA = (lane & 0x1c) | (q >> 1);
    const int srcC = srcA + 2;

    fill(0, 0);
    if (n > 1) fill(1, 1);

    for (int i = 0; i < n; ++i) {
        const int sp = i & 1;
        if (i + 1 < n) cp_wait<1>(); else cp_wait<0>();
        __syncwarp();

        const uint32_t* uK = usm + (warp * 2 + sp) * 1152;
        const uint32_t* uV = uK + 576;
        const int dx = ndxy[i] >> 4, dy = ndxy[i] & 15;

        // ---- QK ----
        float sacc[2][4];
#pragma unroll
        for (int nb = 0; nb < 2; ++nb)
#pragma unroll
            for (int e = 0; e < 4; ++e) sacc[nb][e] = 0.0f;
#pragma unroll
        for (int kc = 0; kc < 4; ++kc) {
#pragma unroll
            for (int nb = 0; nb < 2; ++nb) {
                uint32_t b0 = uK[(nb * 8 + g) * 36 + kc * 8 + q];
                uint32_t b1 = uK[(nb * 8 + g) * 36 + kc * 8 + q + 4];
                mma_tf32(sacc[nb], qa0[kc], qa1[kc], qa2[kc], qa3[kc], b0, b1);
            }
        }

        // ---- bias (exact arithmetic) ----
#pragma unroll
        for (int nb = 0; nb < 2; ++nb)
#pragma unroll
            for (int e = 0; e < 2; ++e) {
                int j = nb * 8 + 2 * q + e, jx = j >> 2, jy = j & 3;
                int ixg = 4 * dx + jx - qx_g - 4,  iyg = 4 * dy + jy - qy_g - 4;
                int ixh = 4 * dx + jx - qx_g8 - 4, iyh = 4 * dy + jy - qy_g8 - 4;
                sacc[nb][e]     -= (float)(ixg * ixg + iyg * iyg) * 0.0625f;
                sacc[nb][e + 2] -= (float)(ixh * ixh + iyh * iyh) * 0.0625f;
            }

        // ---- online softmax (rows g, g+8) ----
        float ml_g  = fmaxf(fmaxf(sacc[0][0], sacc[0][1]), fmaxf(sacc[1][0], sacc[1][1]));
        float ml_g8 = fmaxf(fmaxf(sacc[0][2], sacc[0][3]), fmaxf(sacc[1][2], sacc[1][3]));
        ml_g  = fmaxf(ml_g,  __shfl_xor_sync(0xffffffffu, ml_g, 1));
        ml_g  = fmaxf(ml_g,  __shfl_xor_sync(0xffffffffu, ml_g, 2));
        ml_g8 = fmaxf(ml_g8, __shfl_xor_sync(0xffffffffu, ml_g8, 1));
        ml_g8 = fmaxf(ml_g8, __shfl_xor_sync(0xffffffffu, ml_g8, 2));
        float mn_g  = fmaxf(m_g, ml_g),   cor_g  = __expf(m_g - mn_g);
        float mn_g8 = fmaxf(m_g8, ml_g8), cor_g8 = __expf(m_g8 - mn_g8);
        m_g = mn_g; m_g8 = mn_g8;

        float pp[2][4];
        float ls_g = 0.0f, ls_g8 = 0.0f;
#pragma unroll
        for (int nb = 0; nb < 2; ++nb) {
            pp[nb][0] = __expf(sacc[nb][0] - mn_g);
            pp[nb][1] = __expf(sacc[nb][1] - mn_g);
            pp[nb][2] = __expf(sacc[nb][2] - mn_g8);
            pp[nb][3] = __expf(sacc[nb][3] - mn_g8);
            ls_g  += pp[nb][0] + pp[nb][1];
            ls_g8 += pp[nb][2] + pp[nb][3];
        }
        ls_g  += __shfl_xor_sync(0xffffffffu, ls_g, 1);
        ls_g  += __shfl_xor_sync(0xffffffffu, ls_g, 2);
        ls_g8 += __shfl_xor_sync(0xffffffffu, ls_g8, 1);
        ls_g8 += __shfl_xor_sync(0xffffffffu, ls_g8, 2);
        l_g  = l_g  * cor_g  + ls_g;
        l_g8 = l_g8 * cor_g8 + ls_g8;

#pragma unroll
        for (int nb = 0; nb < 4; ++nb) {
            oacc[nb][0] *= cor_g;  oacc[nb][1] *= cor_g;
            oacc[nb][2] *= cor_g8; oacc[nb][3] *= cor_g8;
        }

        // ---- C-frag -> A-frag via quad shuffles, then PV ----
        uint32_t pt[2][4];
#pragma unroll
        for (int nb = 0; nb < 2; ++nb)
#pragma unroll
            for (int e = 0; e < 4; ++e) pt[nb][e] = to_tf32(pp[nb][e]);

#pragma unroll
        for (int kc = 0; kc < 2; ++kc) {
            uint32_t v0 = __shfl_sync(0xffffffffu, pt[kc][0], srcA);
            uint32_t v1 = __shfl_sync(0xffffffffu, pt[kc][1], srcA);
            uint32_t w0 = __shfl_sync(0xffffffffu, pt[kc][2], srcA);
            uint32_t w1 = __shfl_sync(0xffffffffu, pt[kc][3], srcA);
            uint32_t x0 = __shfl_sync(0xffffffffu, pt[kc][0], srcC);
            uint32_t x1 = __shfl_sync(0xffffffffu, pt[kc][1], srcC);
            uint32_t y0 = __shfl_sync(0xffffffffu, pt[kc][2], srcC);
            uint32_t y1 = __shfl_sync(0xffffffffu, pt[kc][3], srcC);
            uint32_t a0 = (q & 1) ? v1 : v0;
            uint32_t a1 = (q & 1) ? w1 : w0;
            uint32_t a2 = (q & 1) ? x1 : x0;
            uint32_t a3 = (q & 1) ? y1 : y0;
#pragma unroll
            for (int nbd = 0; nbd < 4; ++nbd) {
                uint32_t b0 = uV[(kc * 8 + q) * 36 + nbd * 8 + g];
                uint32_t b1 = uV[(kc * 8 + q + 4) * 36 + nbd * 8 + g];
                mma_tf32(oacc[nbd], a0, a1, a2, a3, b0, b1);
            }
        }

        if (i + 2 < n) fill(i + 2, sp);   // warp-local; no CTA barrier needed
    }

    // ---- normalize, stash O (shared across warps) ----
    __syncthreads();                       // all warps done with their stages
    uint32_t* uO = usm;                    // 16 x 260
    {
        float inv_g = 1.0f / l_g, inv_g8 = 1.0f / l_g8;
#pragma unroll
        for (int nbd = 0; nbd < 4; ++nbd) {
            int c0 = (h << 5) + nbd * 8 + 2 * q;
            uO[g * 260 + c0]           = to_tf32(oacc[nbd][0] * inv_g);
            uO[g * 260 + c0 + 1]       = to_tf32(oacc[nbd][1] * inv_g);
            uO[(g + 8) * 260 + c0]     = to_tf32(oacc[nbd][2] * inv_g8);
            uO[(g + 8) * 260 + c0 + 1] = to_tf32(oacc[nbd][3] * inv_g8);
        }
    }
    __syncthreads();

    // ---- output projection: warp handles channel blocks cb = 2w, 2w+1 ----
    float cacc[2][4];
#pragma unroll
    for (int cb = 0; cb < 2; ++cb)
#pragma unroll
        for (int e = 0; e < 4; ++e) cacc[cb][e] = 0.0f;

#pragma unroll 8
    for (int kc = 0; kc < 32; ++kc) {
        uint32_t a0 = uO[g * 260 + kc * 8 + q];
        uint32_t a1 = uO[(g + 8) * 260 + kc * 8 + q];
        uint32_t a2 = uO[g * 260 + kc * 8 + q + 4];
        uint32_t a3 = uO[(g + 8) * 260 + kc * 8 + q + 4];
#pragma unroll
        for (int cbi = 0; cbi < 2; ++cbi) {
            u64 w2 = g_wofrag[(((warp * 2 + cbi) << 5) + kc) * 32 + lane];
            mma_tf32(cacc[cbi], a0, a1, a2, a3,
                     (uint32_t)(w2 & 0xffffffffu), (uint32_t)(w2 >> 32));
        }
    }

    // ---- + b_out, store out[b][c][h=vb*4+py][w=hb*4+px] ----
    const size_t ob = ((size_t)b << 23) + (size_t)(vb * 4) * 256 + hb * 4;
    const int pxg = g >> 2, pyg = g & 3;
    const int pxg8 = (g + 8) >> 2, pyg8 = (g + 8) & 3;
#pragma unroll
    for (int cbi = 0; cbi < 2; ++cbi) {
#pragma unroll
        for (int e = 0; e < 2; ++e) {
            int c = (warp * 2 + cbi) * 8 + 2 * q + e;
            float bo = __ldg(&b_out[c]);
            out[ob + (size_t)c * 65536 + pyg * 256 + pxg]   = cacc[cbi][e] + bo;
            out[ob + (size_t)c * 65536 + pyg8 * 256 + pxg8] = cacc[cbi][e + 2] + bo;
        }
    }
}

// ---------------------------------------------------------------------------
extern "C" void kernel_launch(void* const* d_in, const int* in_sizes, int n_in,
                              void* d_out, int out_size) {
    (void)in_sizes; (void)n_in; (void)out_size;
    const float* x     = (const float*)d_in[0];
    const float* w_in  = (const float*)d_in[1];
    const float* b_in  = (const float*)d_in[2];
    const float* w_out = (const float*)d_in[3];
    const float* b_out = (const float*)d_in[4];
    float* out = (float*)d_out;

    static int configured = 0;
    if (!configured) {
        cudaFuncSetAttribute(attn_mma_kernel, cudaFuncAttributeMaxDynamicSharedMemorySize, 73728);
        configured = 1;
    }

    wfrag_kernel<<<96, 256>>>(w_in);
    wofrag_kernel<<<64, 256>>>(w_out);
    proj_mma_kernel<<<2048, 256>>>(x, b_in);
    attn_mma_kernel<<<8192, 256, 73728>>>(b_out, out);
}

// round 14
// speedup vs baseline: 2.1336x; 1.1621x over previous
#include <cuda_runtime.h>
#include <cstdint>

// AttentionConvolution2D: B=2, DIN=128, H=W=256, BS=4, NH=8, DH=32, DOUT=128
typedef unsigned long long u64;

__device__ __forceinline__ uint32_t to_tf32(float f) {
    uint32_t r; asm("cvt.rna.tf32.f32 %0, %1;" : "=r"(r) : "f"(f)); return r;
}
__device__ __forceinline__ void mma_tf32(float* d,
                                         uint32_t a0, uint32_t a1, uint32_t a2, uint32_t a3,
                                         uint32_t b0, uint32_t b1) {
    asm("mma.sync.aligned.m16n8k8.row.col.f32.tf32.tf32.f32 "
        "{%0,%1,%2,%3}, {%4,%5,%6,%7}, {%8,%9}, {%0,%1,%2,%3};"
        : "+f"(d[0]), "+f"(d[1]), "+f"(d[2]), "+f"(d[3])
        : "r"(a0), "r"(a1), "r"(a2), "r"(a3), "r"(b0), "r"(b1));
}
__device__ __forceinline__ void cpa16(uint32_t dst, const void* src) {
    asm volatile("cp.async.cg.shared.global [%0], [%1], 16;" :: "r"(dst), "l"(src));
}
__device__ __forceinline__ void cp_commit() {
    asm volatile("cp.async.commit_group;");
}
template <int N> __device__ __forceinline__ void cp_wait() {
    asm volatile("cp.async.wait_group %0;" :: "n"(N));
}

// proj scratch, tile-major, TF32 BIT PATTERNS (q pre-scaled by 1/sqrt(32)):
// tile=(b*64+hb)*64+vb, row=pixel pi=(w&3)*4+(h&3), 768 ch/row (q|k|v)
// After attn, the q slot of each tile holds that tile's normalized O (tf32).
__device__ float g_proj[100663296];     // 131072*768 words
__device__ uint32_t g_wfrag[98304];     // w_in  in m16n8k8 A-fragment order (tf32)
__device__ u64 g_wofrag[16384];         // w_out in m16n8k8 B-fragment order (tf32 pairs)

// ---------------- K1a: pack w_in (768x128) into A-fragment order -------------
__global__ void wfrag_kernel(const float* __restrict__ w_in) {
    int idx = blockIdx.x * 256 + threadIdx.x;     // 0..24575
    if (idx >= 24576) return;
    int lane = idx & 31, kk = (idx >> 5) & 15, mb = idx >> 9;
    int g = lane >> 2, q = lane & 3;
    int r0 = mb * 16 + g, r1 = r0 + 8;
    int c0 = kk * 8 + q,  c1 = c0 + 4;
    uint4 o;
    o.x = to_tf32(w_in[r0 * 128 + c0]);
    o.y = to_tf32(w_in[r1 * 128 + c0]);
    o.z = to_tf32(w_in[r0 * 128 + c1]);
    o.w = to_tf32(w_in[r1 * 128 + c1]);
    *(uint4*)&g_wfrag[idx * 4] = o;
}

// ---------------- K1b: pack w_out (128x256) into B-fragment order ------------
__global__ void wofrag_kernel(const float* __restrict__ w_out) {
    int f = blockIdx.x * 256 + threadIdx.x;       // 0..16383
    if (f >= 16384) return;
    int lane = f & 31, kc = (f >> 5) & 31, cb = f >> 10;
    int g = lane >> 2, q = lane & 3;
    int c = cb * 8 + g;
    uint32_t b0 = to_tf32(w_out[c * 256 + kc * 8 + q]);
    uint32_t b1 = to_tf32(w_out[c * 256 + kc * 8 + q + 4]);
    g_wofrag[f] = (u64)b0 | ((u64)b1 << 32);
}

// ---------------- K2: projection GEMM via tf32 MMA (R9 64px, known-good) -----
__global__ __launch_bounds__(256) void proj_mma_kernel(const float* __restrict__ x,
                                                       const float* __restrict__ b_in) {
    __shared__ uint32_t sB[128 * 72];   // 36864 B

    const int t   = threadIdx.x;
    const int pbk = blockIdx.x;           // 0..2047
    const int b   = pbk >> 10;
    const int rem = pbk & 1023;
    const int hc  = rem >> 2;             // h 0..255
    const int w0  = (rem & 3) << 6;       // first w of strip

    const float* xb = x + ((size_t)b << 23) + (size_t)hc * 256 + w0;

#pragma unroll
    for (int r = 0; r < 8; ++r) {
        int flat = r * 1024 + t * 4;
        int k = flat >> 6, px = flat & 63;
        float4 v = *(const float4*)&xb[(size_t)k * 65536 + px];
        uint4 o = { to_tf32(v.x), to_tf32(v.y), to_tf32(v.z), to_tf32(v.w) };
        *(uint4*)&sB[k * 72 + px] = o;
    }
    __syncthreads();

    const int warp = t >> 5, lane = t & 31;
    const int wm = warp >> 1, wn = warp & 1;
    const int nw0 = wn << 5;
    const int g = lane >> 2, q = lane & 3;

    const int vbb = hc >> 2, py = hc & 3;
    size_t pxbase[4][2];
#pragma unroll
    for (int nb = 0; nb < 4; ++nb)
#pragma unroll
        for (int e = 0; e < 2; ++e) {
            int i  = nw0 + nb * 8 + 2 * q + e;
            int w  = w0 + i;
            int hb = w >> 2, pxm = w & 3;
            pxbase[nb][e] = ((((size_t)b * 64 + hb) * 64 + vbb) * 16 + pxm * 4 + py) * 768;
        }

    const float SCALE = 0.17677669529663687f;   // 1/sqrt(32)

    for (int nbk = 0; nbk < 6; ++nbk) {
        const int mbase = nbk * 8 + wm * 2;
        const float sc = (nbk < 2) ? SCALE : 1.0f;
        float acc[2][4][4];
#pragma unroll
        for (int m = 0; m < 2; ++m)
#pragma unroll
            for (int nb = 0; nb < 4; ++nb)
#pragma unroll
                for (int e = 0; e < 4; ++e) acc[m][nb][e] = 0.0f;

#pragma unroll
        for (int kk = 0; kk < 16; ++kk) {
            uint4 a0 = *(const uint4*)&g_wfrag[(((mbase + 0) * 16 + kk) * 32 + lane) * 4];
            uint4 a1 = *(const uint4*)&g_wfrag[(((mbase + 1) * 16 + kk) * 32 + lane) * 4];
            const int rb0 = (kk * 8 + q) * 72 + nw0 + g;
#pragma unroll
            for (int nb = 0; nb < 4; ++nb) {
                uint32_t bf0 = sB[rb0 + nb * 8];
                uint32_t bf1 = sB[rb0 + 288 + nb * 8];
                mma_tf32(acc[0][nb], a0.x, a0.y, a0.z, a0.w, bf0, bf1);
                mma_tf32(acc[1][nb], a1.x, a1.y, a1.z, a1.w, bf0, bf1);
            }
        }

#pragma unroll
        for (int m = 0; m < 2; ++m) {
            int ch0 = nbk * 128 + (wm * 2 + m) * 16 + g;
            float bias0 = b_in[ch0];
            float bias1 = b_in[ch0 + 8];
#pragma unroll
            for (int nb = 0; nb < 4; ++nb) {
                g_proj[pxbase[nb][0] + ch0]     = __uint_as_float(to_tf32((acc[m][nb][0] + bias0) * sc));
                g_proj[pxbase[nb][1] + ch0]     = __uint_as_float(to_tf32((acc[m][nb][1] + bias0) * sc));
                g_proj[pxbase[nb][0] + ch0 + 8] = __uint_as_float(to_tf32((acc[m][nb][2] + bias1) * sc));
                g_proj[pxbase[nb][1] + ch0 + 8] = __uint_as_float(to_tf32((acc[m][nb][3] + bias1) * sc));
            }
        }
    }
}

// ---------------- K3: attention mainloop (R10 staging), O -> g_proj q-slot ---
#define STAGE_WORDS 8512

__global__ __launch_bounds__(256, 3) void attn_mma_kernel() {
    extern __shared__ uint32_t usm[];

    const int bid = blockIdx.x;
    const int vb = bid & 63;
    const int hb = (bid >> 6) & 63;
    const int b  = bid >> 12;
    const int t  = threadIdx.x;
    const int warp = t >> 5, lane = t & 31;
    const int h = warp;
    const int g = lane >> 2, q = lane & 3;

    uint32_t* tbu = (uint32_t*)g_proj + (size_t)bid * 12288;

    // ---- Q fragments straight into registers (tf32 bits, pre-scaled) ----
    uint32_t qa0[4], qa1[4], qa2[4], qa3[4];
#pragma unroll
    for (int kc = 0; kc < 4; ++kc) {
        int base = (h << 5) + kc * 8 + q;
        qa0[kc] = tbu[g * 768 + base];
        qa1[kc] = tbu[(g + 8) * 768 + base];
        qa2[kc] = tbu[g * 768 + base + 4];
        qa3[kc] = tbu[(g + 8) * 768 + base + 4];
    }

    // ---- valid neighbor list ----
    int nidx[9], ndxy[9], n = 0;
    for (int dx = 0; dx < 3; ++dx) {
        int nhb = hb + dx - 1;
        if ((unsigned)nhb >= 64u) continue;      // boundary == -inf mask
        for (int dy = 0; dy < 3; ++dy) {
            int nvb = vb + dy - 1;
            if ((unsigned)nvb >= 64u) continue;
            nidx[n] = (b << 12) + (nhb << 6) + nvb;
            ndxy[n] = (dx << 4) | dy;
            ++n;
        }
    }

    const uint32_t aS = (uint32_t)__cvta_generic_to_shared(usm);

    auto fill = [&](int i, int sp) {
        const float* nb_ = g_proj + (size_t)nidx[i] * 12288 + 256;
        uint32_t bs = aS + sp * (STAGE_WORDS * 4);
#pragma unroll
        for (int r = 0; r < 4; ++r) {
            int flat = r * 1024 + t * 4;
            int key = flat >> 8, ch = flat & 255;
            cpa16(bs + (key * 268 + ch) * 4, nb_ + key * 768 + ch);
            cpa16(bs + (4288 + key * 264 + ch) * 4, nb_ + key * 768 + 256 + ch);
        }
        cp_commit();
    };

    float oacc[4][4];
#pragma unroll
    for (int nb = 0; nb < 4; ++nb)
#pragma unroll
        for (int e = 0; e < 4; ++e) oacc[nb][e] = 0.0f;
    float m_g = -1e30f, m_g8 = -1e30f, l_g = 0.0f, l_g8 = 0.0f;

    const int qx_g  = g >> 2,       qy_g  = g & 3;
    const int qx_g8 = (g + 8) >> 2, qy_g8 = (g + 8) & 3;
    const int srcA = (lane & 0x1c) | (q >> 1);
    const int srcC = srcA + 2;

    fill(0, 0);
    if (n > 1) fill(1, 1);

    for (int i = 0; i < n; ++i) {
        const int sp = i & 1;
        if (i + 1 < n) cp_wait<1>(); else cp_wait<0>();
        __syncthreads();

        const uint32_t* uK = usm + sp * STAGE_WORDS;
        const uint32_t* uV = uK + 4288;
        const int dx = ndxy[i] >> 4, dy = ndxy[i] & 15;

        // ---- QK ----
        float sacc[2][4];
#pragma unroll
        for (int nb = 0; nb < 2; ++nb)
#pragma unroll
            for (int e = 0; e < 4; ++e) sacc[nb][e] = 0.0f;
#pragma unroll
        for (int kc = 0; kc < 4; ++kc) {
#pragma unroll
            for (int nb = 0; nb < 2; ++nb) {
                uint32_t b0 = uK[(nb * 8 + g) * 268 + (h << 5) + kc * 8 + q];
                uint32_t b1 = uK[(nb * 8 + g) * 268 + (h << 5) + kc * 8 + q + 4];
                mma_tf32(sacc[nb], qa0[kc], qa1[kc], qa2[kc], qa3[kc], b0, b1);
            }
        }

        // ---- bias (exact arithmetic) ----
#pragma unroll
        for (int nb = 0; nb < 2; ++nb)
#pragma unroll
            for (int e = 0; e < 2; ++e) {
                int j = nb * 8 + 2 * q + e, jx = j >> 2, jy = j & 3;
                int ixg = 4 * dx + jx - qx_g - 4,  iyg = 4 * dy + jy - qy_g - 4;
                int ixh = 4 * dx + jx - qx_g8 - 4, iyh = 4 * dy + jy - qy_g8 - 4;
                sacc[nb][e]     -= (float)(ixg * ixg + iyg * iyg) * 0.0625f;
                sacc[nb][e + 2] -= (float)(ixh * ixh + iyh * iyh) * 0.0625f;
            }

        // ---- online softmax (rows g, g+8) ----
        float ml_g  = fmaxf(fmaxf(sacc[0][0], sacc[0][1]), fmaxf(sacc[1][0], sacc[1][1]));
        float ml_g8 = fmaxf(fmaxf(sacc[0][2], sacc[0][3]), fmaxf(sacc[1][2], sacc[1][3]));
        ml_g  = fmaxf(ml_g,  __shfl_xor_sync(0xffffffffu, ml_g, 1));
        ml_g  = fmaxf(ml_g,  __shfl_xor_sync(0xffffffffu, ml_g, 2));
        ml_g8 = fmaxf(ml_g8, __shfl_xor_sync(0xffffffffu, ml_g8, 1));
        ml_g8 = fmaxf(ml_g8, __shfl_xor_sync(0xffffffffu, ml_g8, 2));
        float mn_g  = fmaxf(m_g, ml_g),   cor_g  = __expf(m_g - mn_g);
        float mn_g8 = fmaxf(m_g8, ml_g8), cor_g8 = __expf(m_g8 - mn_g8);
        m_g = mn_g; m_g8 = mn_g8;

        float pp[2][4];
        float ls_g = 0.0f, ls_g8 = 0.0f;
#pragma unroll
        for (int nb = 0; nb < 2; ++nb) {
            pp[nb][0] = __expf(sacc[nb][0] - mn_g);
            pp[nb][1] = __expf(sacc[nb][1] - mn_g);
            pp[nb][2] = __expf(sacc[nb][2] - mn_g8);
            pp[nb][3] = __expf(sacc[nb][3] - mn_g8);
            ls_g  += pp[nb][0] + pp[nb][1];
            ls_g8 += pp[nb][2] + pp[nb][3];
        }
        ls_g  += __shfl_xor_sync(0xffffffffu, ls_g, 1);
        ls_g  += __shfl_xor_sync(0xffffffffu, ls_g, 2);
        ls_g8 += __shfl_xor_sync(0xffffffffu, ls_g8, 1);
        ls_g8 += __shfl_xor_sync(0xffffffffu, ls_g8, 2);
        l_g  = l_g  * cor_g  + ls_g;
        l_g8 = l_g8 * cor_g8 + ls_g8;

#pragma unroll
        for (int nb = 0; nb < 4; ++nb) {
            oacc[nb][0] *= cor_g;  oacc[nb][1] *= cor_g;
            oacc[nb][2] *= cor_g8; oacc[nb][3] *= cor_g8;
        }

        // ---- C-frag -> A-frag via quad shuffles, then PV ----
        uint32_t pt[2][4];
#pragma unroll
        for (int nb = 0; nb < 2; ++nb)
#pragma unroll
            for (int e = 0; e < 4; ++e) pt[nb][e] = to_tf32(pp[nb][e]);

#pragma unroll
        for (int kc = 0; kc < 2; ++kc) {
            uint32_t v0 = __shfl_sync(0xffffffffu, pt[kc][0], srcA);
            uint32_t v1 = __shfl_sync(0xffffffffu, pt[kc][1], srcA);
            uint32_t w0 = __shfl_sync(0xffffffffu, pt[kc][2], srcA);
            uint32_t w1 = __shfl_sync(0xffffffffu, pt[kc][3], srcA);
            uint32_t x0 = __shfl_sync(0xffffffffu, pt[kc][0], srcC);
            uint32_t x1 = __shfl_sync(0xffffffffu, pt[kc][1], srcC);
            uint32_t y0 = __shfl_sync(0xffffffffu, pt[kc][2], srcC);
            uint32_t y1 = __shfl_sync(0xffffffffu, pt[kc][3], srcC);
            uint32_t a0 = (q & 1) ? v1 : v0;
            uint32_t a1 = (q & 1) ? w1 : w0;
            uint32_t a2 = (q & 1) ? x1 : x0;
            uint32_t a3 = (q & 1) ? y1 : y0;
#pragma unroll
            for (int nbd = 0; nbd < 4; ++nbd) {
                uint32_t b0 = uV[(kc * 8 + q) * 264 + (h << 5) + nbd * 8 + g];
                uint32_t b1 = uV[(kc * 8 + q + 4) * 264 + (h << 5) + nbd * 8 + g];
                mma_tf32(oacc[nbd], a0, a1, a2, a3, b0, b1);
            }
        }

        __syncthreads();
        if (i + 2 < n) fill(i + 2, sp);
    }

    // ---- normalize, write O (tf32 bits) into this tile's q-slot -------------
    {
        float inv_g = 1.0f / l_g, inv_g8 = 1.0f / l_g8;
#pragma unroll
        for (int nbd = 0; nbd < 4; ++nbd) {
            int c0 = (h << 5) + nbd * 8 + 2 * q;
            u64 w0 = (u64)to_tf32(oacc[nbd][0] * inv_g)
                   | ((u64)to_tf32(oacc[nbd][1] * inv_g) << 32);
            u64 w1 = (u64)to_tf32(oacc[nbd][2] * inv_g8)
                   | ((u64)to_tf32(oacc[nbd][3] * inv_g8) << 32);
            *(u64*)&tbu[g * 768 + c0]       = w0;
            *(u64*)&tbu[(g + 8) * 768 + c0] = w1;
        }
    }
}

// ---------------- K4: output projection, 4 tiles per CTA ---------------------
// Stages 4 O-tiles (16x256 tf32 each) into smem (stride 260), then per kc each
// weight fragment is loaded ONCE and reused across all 4 tiles (weight L2
// traffic: 1.07GB -> 262MB vs fused epilogue).
__global__ __launch_bounds__(256, 3) void outproj_mma_kernel(const float* __restrict__ b_out,
                                                             float* __restrict__ out) {
    extern __shared__ uint32_t sO[];    // 4 x 16 x 260 = 16640 words (66560 B)

    const int t = threadIdx.x;
    const int warp = t >> 5, lane = t & 31;
    const int g = lane >> 2, q = lane & 3;
    const int tile0 = blockIdx.x * 4;

    const uint32_t aO = (uint32_t)__cvta_generic_to_shared(sO);
#pragma unroll
    for (int r = 0; r < 16; ++r) {
        int flat = r * 1024 + t * 4;            // 0..16383
        int tile = flat >> 12;
        int rem = flat & 4095;
        int row = rem >> 8, ch = rem & 255;
        const float* src = g_proj + (size_t)(tile0 + tile) * 12288 + row * 768 + ch;
        cpa16(aO + (tile * 4160 + row * 260 + ch) * 4, src);
    }
    cp_commit();
    cp_wait<0>();
    __syncthreads();

    float cacc[2][4][4];                        // [cbi][tile][e]
#pragma unroll
    for (int cb = 0; cb < 2; ++cb)
#pragma unroll
        for (int tt = 0; tt < 4; ++tt)
#pragma unroll
            for (int e = 0; e < 4; ++e) cacc[cb][tt][e] = 0.0f;

#pragma unroll 4
    for (int kc = 0; kc < 32; ++kc) {
        u64 w2a = g_wofrag[(((warp * 2 + 0) << 5) + kc) * 32 + lane];
        u64 w2b = g_wofrag[(((warp * 2 + 1) << 5) + kc) * 32 + lane];
        uint32_t ba0 = (uint32_t)(w2a & 0xffffffffu), ba1 = (uint32_t)(w2a >> 32);
        uint32_t bb0 = (uint32_t)(w2b & 0xffffffffu), bb1 = (uint32_t)(w2b >> 32);
#pragma unroll
        for (int tt = 0; tt < 4; ++tt) {
            const uint32_t* uO = sO + tt * 4160;
            uint32_t a0 = uO[g * 260 + kc * 8 + q];
            uint32_t a1 = uO[(g + 8) * 260 + kc * 8 + q];
            uint32_t a2 = uO[g * 260 + kc * 8 + q + 4];
            uint32_t a3 = uO[(g + 8) * 260 + kc * 8 + q + 4];
            mma_tf32(cacc[0][tt], a0, a1, a2, a3, ba0, ba1);
            mma_tf32(cacc[1][tt], a0, a1, a2, a3, bb0, bb1);
        }
    }

    const int pxg = g >> 2, pyg = g & 3;
    const int pxg8 = (g + 8) >> 2, pyg8 = (g + 8) & 3;
#pragma unroll
    for (int tt = 0; tt < 4; ++tt) {
        int bid = tile0 + tt;
        int vb = bid & 63, hb = (bid >> 6) & 63, b = bid >> 12;
        size_t ob = ((size_t)b << 23) + (size_t)(vb * 4) * 256 + hb * 4;
#pragma unroll
        for (int cbi = 0; cbi < 2; ++cbi) {
#pragma unroll
            for (int e = 0; e < 2; ++e) {
                int c = (warp * 2 + cbi) * 8 + 2 * q + e;
                float bo = __ldg(&b_out[c]);
                out[ob + (size_t)c * 65536 + pyg * 256 + pxg]   = cacc[cbi][tt][e] + bo;
                out[ob + (size_t)c * 65536 + pyg8 * 256 + pxg8] = cacc[cbi][tt][e + 2] + bo;
            }
        }
    }
}

// ---------------------------------------------------------------------------
extern "C" void kernel_launch(void* const* d_in, const int* in_sizes, int n_in,
                              void* d_out, int out_size) {
    (void)in_sizes; (void)n_in; (void)out_size;
    const float* x     = (const float*)d_in[0];
    const float* w_in  = (const float*)d_in[1];
    const float* b_in  = (const float*)d_in[2];
    const float* w_out = (const float*)d_in[3];
    const float* b_out = (const float*)d_in[4];
    float* out = (float*)d_out;

    static int configured = 0;
    if (!configured) {
        cudaFuncSetAttribute(attn_mma_kernel, cudaFuncAttributeMaxDynamicSharedMemorySize, 69632);
        cudaFuncSetAttribute(outproj_mma_kernel, cudaFuncAttributeMaxDynamicSharedMemorySize, 66560);
        configured = 1;
    }

    wfrag_kernel<<<96, 256>>>(w_in);
    wofrag_kernel<<<64, 256>>>(w_out);
    proj_mma_kernel<<<2048, 256>>>(x, b_in);
    attn_mma_kernel<<<8192, 256, 68096>>>();
    outproj_mma_kernel<<<2048, 256, 66560>>>(b_out, out);
}

// round 15
// speedup vs baseline: 2.2032x; 1.0326x over previous
#include <cuda_runtime.h>
#include <cstdint>

// AttentionConvolution2D: B=2, DIN=128, H=W=256, BS=4, NH=8, DH=32, DOUT=128
typedef unsigned long long u64;

__device__ __forceinline__ uint32_t to_tf32(float f) {
    uint32_t r; asm("cvt.rna.tf32.f32 %0, %1;" : "=r"(r) : "f"(f)); return r;
}
__device__ __forceinline__ void mma_tf32(float* d,
                                         uint32_t a0, uint32_t a1, uint32_t a2, uint32_t a3,
                                         uint32_t b0, uint32_t b1) {
    asm("mma.sync.aligned.m16n8k8.row.col.f32.tf32.tf32.f32 "
        "{%0,%1,%2,%3}, {%4,%5,%6,%7}, {%8,%9}, {%0,%1,%2,%3};"
        : "+f"(d[0]), "+f"(d[1]), "+f"(d[2]), "+f"(d[3])
        : "r"(a0), "r"(a1), "r"(a2), "r"(a3), "r"(b0), "r"(b1));
}
__device__ __forceinline__ void cpa16(uint32_t dst, const void* src) {
    asm volatile("cp.async.cg.shared.global [%0], [%1], 16;" :: "r"(dst), "l"(src));
}
__device__ __forceinline__ void cp_commit() {
    asm volatile("cp.async.commit_group;");
}
template <int N> __device__ __forceinline__ void cp_wait() {
    asm volatile("cp.async.wait_group %0;" :: "n"(N));
}

// proj scratch, tile-major, TF32 BIT PATTERNS (q pre-scaled by 1/sqrt(32)):
// tile=(b*64+hb)*64+vb, row=pixel pi=(w&3)*4+(h&3), 768 ch/row (q|k|v)
// After attn, the q slot of each tile holds that tile's normalized O (tf32).
__device__ float g_proj[100663296];     // 131072*768 words
__device__ uint32_t g_wfrag[98304];     // w_in  in m16n8k8 A-fragment order (tf32)
__device__ u64 g_wofrag[16384];         // w_out in m16n8k8 B-fragment order (tf32 pairs)

// ---------------- K1a: pack w_in (768x128) into A-fragment order -------------
__global__ void wfrag_kernel(const float* __restrict__ w_in) {
    int idx = blockIdx.x * 256 + threadIdx.x;     // 0..24575
    if (idx >= 24576) return;
    int lane = idx & 31, kk = (idx >> 5) & 15, mb = idx >> 9;
    int g = lane >> 2, q = lane & 3;
    int r0 = mb * 16 + g, r1 = r0 + 8;
    int c0 = kk * 8 + q,  c1 = c0 + 4;
    uint4 o;
    o.x = to_tf32(w_in[r0 * 128 + c0]);
    o.y = to_tf32(w_in[r1 * 128 + c0]);
    o.z = to_tf32(w_in[r0 * 128 + c1]);
    o.w = to_tf32(w_in[r1 * 128 + c1]);
    *(uint4*)&g_wfrag[idx * 4] = o;
}

// ---------------- K1b: pack w_out (128x256) into B-fragment order ------------
__global__ void wofrag_kernel(const float* __restrict__ w_out) {
    int f = blockIdx.x * 256 + threadIdx.x;       // 0..16383
    if (f >= 16384) return;
    int lane = f & 31, kc = (f >> 5) & 31, cb = f >> 10;
    int g = lane >> 2, q = lane & 3;
    int c = cb * 8 + g;
    uint32_t b0 = to_tf32(w_out[c * 256 + kc * 8 + q]);
    uint32_t b1 = to_tf32(w_out[c * 256 + kc * 8 + q + 4]);
    g_wofrag[f] = (u64)b0 | ((u64)b1 << 32);
}

// ---------------- K2: projection GEMM via tf32 MMA (R9 64px, known-good) -----
__global__ __launch_bounds__(256) void proj_mma_kernel(const float* __restrict__ x,
                                                       const float* __restrict__ b_in) {
    __shared__ uint32_t sB[128 * 72];   // 36864 B

    const int t   = threadIdx.x;
    const int pbk = blockIdx.x;           // 0..2047
    const int b   = pbk >> 10;
    const int rem = pbk & 1023;
    const int hc  = rem >> 2;             // h 0..255
    const int w0  = (rem & 3) << 6;       // first w of strip

    const float* xb = x + ((size_t)b << 23) + (size_t)hc * 256 + w0;

#pragma unroll
    for (int r = 0; r < 8; ++r) {
        int flat = r * 1024 + t * 4;
        int k = flat >> 6, px = flat & 63;
        float4 v = *(const float4*)&xb[(size_t)k * 65536 + px];
        uint4 o = { to_tf32(v.x), to_tf32(v.y), to_tf32(v.z), to_tf32(v.w) };
        *(uint4*)&sB[k * 72 + px] = o;
    }
    __syncthreads();

    const int warp = t >> 5, lane = t & 31;
    const int wm = warp >> 1, wn = warp & 1;
    const int nw0 = wn << 5;
    const int g = lane >> 2, q = lane & 3;

    const int vbb = hc >> 2, py = hc & 3;
    size_t pxbase[4][2];
#pragma unroll
    for (int nb = 0; nb < 4; ++nb)
#pragma unroll
        for (int e = 0; e < 2; ++e) {
            int i  = nw0 + nb * 8 + 2 * q + e;
            int w  = w0 + i;
            int hb = w >> 2, pxm = w & 3;
            pxbase[nb][e] = ((((size_t)b * 64 + hb) * 64 + vbb) * 16 + pxm * 4 + py) * 768;
        }

    const float SCALE = 0.17677669529663687f;   // 1/sqrt(32)

    for (int nbk = 0; nbk < 6; ++nbk) {
        const int mbase = nbk * 8 + wm * 2;
        const float sc = (nbk < 2) ? SCALE : 1.0f;
        float acc[2][4][4];
#pragma unroll
        for (int m = 0; m < 2; ++m)
#pragma unroll
            for (int nb = 0; nb < 4; ++nb)
#pragma unroll
                for (int e = 0; e < 4; ++e) acc[m][nb][e] = 0.0f;

#pragma unroll
        for (int kk = 0; kk < 16; ++kk) {
            uint4 a0 = *(const uint4*)&g_wfrag[(((mbase + 0) * 16 + kk) * 32 + lane) * 4];
            uint4 a1 = *(const uint4*)&g_wfrag[(((mbase + 1) * 16 + kk) * 32 + lane) * 4];
            const int rb0 = (kk * 8 + q) * 72 + nw0 + g;
#pragma unroll
            for (int nb = 0; nb < 4; ++nb) {
                uint32_t bf0 = sB[rb0 + nb * 8];
                uint32_t bf1 = sB[rb0 + 288 + nb * 8];
                mma_tf32(acc[0][nb], a0.x, a0.y, a0.z, a0.w, bf0, bf1);
                mma_tf32(acc[1][nb], a1.x, a1.y, a1.z, a1.w, bf0, bf1);
            }
        }

#pragma unroll
        for (int m = 0; m < 2; ++m) {
            int ch0 = nbk * 128 + (wm * 2 + m) * 16 + g;
            float bias0 = b_in[ch0];
            float bias1 = b_in[ch0 + 8];
#pragma unroll
            for (int nb = 0; nb < 4; ++nb) {
                g_proj[pxbase[nb][0] + ch0]     = __uint_as_float(to_tf32((acc[m][nb][0] + bias0) * sc));
                g_proj[pxbase[nb][1] + ch0]     = __uint_as_float(to_tf32((acc[m][nb][1] + bias0) * sc));
                g_proj[pxbase[nb][0] + ch0 + 8] = __uint_as_float(to_tf32((acc[m][nb][2] + bias1) * sc));
                g_proj[pxbase[nb][1] + ch0 + 8] = __uint_as_float(to_tf32((acc[m][nb][3] + bias1) * sc));
            }
        }
    }
}

// ---------------- K3: attention mainloop (R10 staging), O -> g_proj q-slot ---
#define STAGE_WORDS 8512

__global__ __launch_bounds__(256, 3) void attn_mma_kernel() {
    extern __shared__ uint32_t usm[];

    const int bid = blockIdx.x;
    const int vb = bid & 63;
    const int hb = (bid >> 6) & 63;
    const int b  = bid >> 12;
    const int t  = threadIdx.x;
    const int warp = t >> 5, lane = t & 31;
    const int h = warp;
    const int g = lane >> 2, q = lane & 3;

    uint32_t* tbu = (uint32_t*)g_proj + (size_t)bid * 12288;

    // ---- Q fragments straight into registers (tf32 bits, pre-scaled) ----
    uint32_t qa0[4], qa1[4], qa2[4], qa3[4];
#pragma unroll
    for (int kc = 0; kc < 4; ++kc) {
        int base = (h << 5) + kc * 8 + q;
        qa0[kc] = tbu[g * 768 + base];
        qa1[kc] = tbu[(g + 8) * 768 + base];
        qa2[kc] = tbu[g * 768 + base + 4];
        qa3[kc] = tbu[(g + 8) * 768 + base + 4];
    }

    // ---- valid neighbor list ----
    int nidx[9], ndxy[9], n = 0;
    for (int dx = 0; dx < 3; ++dx) {
        int nhb = hb + dx - 1;
        if ((unsigned)nhb >= 64u) continue;      // boundary == -inf mask
        for (int dy = 0; dy < 3; ++dy) {
            int nvb = vb + dy - 1;
            if ((unsigned)nvb >= 64u) continue;
            nidx[n] = (b << 12) + (nhb << 6) + nvb;
            ndxy[n] = (dx << 4) | dy;
            ++n;
        }
    }

    const uint32_t aS = (uint32_t)__cvta_generic_to_shared(usm);

    auto fill = [&](int i, int sp) {
        const float* nb_ = g_proj + (size_t)nidx[i] * 12288 + 256;
        uint32_t bs = aS + sp * (STAGE_WORDS * 4);
#pragma unroll
        for (int r = 0; r < 4; ++r) {
            int flat = r * 1024 + t * 4;
            int key = flat >> 8, ch = flat & 255;
            cpa16(bs + (key * 268 + ch) * 4, nb_ + key * 768 + ch);
            cpa16(bs + (4288 + key * 264 + ch) * 4, nb_ + key * 768 + 256 + ch);
        }
        cp_commit();
    };

    float oacc[4][4];
#pragma unroll
    for (int nb = 0; nb < 4; ++nb)
#pragma unroll
        for (int e = 0; e < 4; ++e) oacc[nb][e] = 0.0f;
    float m_g = -1e30f, m_g8 = -1e30f, l_g = 0.0f, l_g8 = 0.0f;

    const int qx_g  = g >> 2,       qy_g  = g & 3;
    const int qx_g8 = (g + 8) >> 2, qy_g8 = (g + 8) & 3;
    const int srcA = (lane & 0x1c) | (q >> 1);
    const int srcC = srcA + 2;

    fill(0, 0);
    if (n > 1) fill(1, 1);

    for (int i = 0; i < n; ++i) {
        const int sp = i & 1;
        if (i + 1 < n) cp_wait<1>(); else cp_wait<0>();
        __syncthreads();

        const uint32_t* uK = usm + sp * STAGE_WORDS;
        const uint32_t* uV = uK + 4288;
        const int dx = ndxy[i] >> 4, dy = ndxy[i] & 15;

        // ---- QK ----
        float sacc[2][4];
#pragma unroll
        for (int nb = 0; nb < 2; ++nb)
#pragma unroll
            for (int e = 0; e < 4; ++e) sacc[nb][e] = 0.0f;
#pragma unroll
        for (int kc = 0; kc < 4; ++kc) {
#pragma unroll
            for (int nb = 0; nb < 2; ++nb) {
                uint32_t b0 = uK[(nb * 8 + g) * 268 + (h << 5) + kc * 8 + q];
                uint32_t b1 = uK[(nb * 8 + g) * 268 + (h << 5) + kc * 8 + q + 4];
                mma_tf32(sacc[nb], qa0[kc], qa1[kc], qa2[kc], qa3[kc], b0, b1);
            }
        }

        // ---- bias (exact arithmetic) ----
#pragma unroll
        for (int nb = 0; nb < 2; ++nb)
#pragma unroll
            for (int e = 0; e < 2; ++e) {
                int j = nb * 8 + 2 * q + e, jx = j >> 2, jy = j & 3;
                int ixg = 4 * dx + jx - qx_g - 4,  iyg = 4 * dy + jy - qy_g - 4;
                int ixh = 4 * dx + jx - qx_g8 - 4, iyh = 4 * dy + jy - qy_g8 - 4;
                sacc[nb][e]     -= (float)(ixg * ixg + iyg * iyg) * 0.0625f;
                sacc[nb][e + 2] -= (float)(ixh * ixh + iyh * iyh) * 0.0625f;
            }

        // ---- online softmax (rows g, g+8) ----
        float ml_g  = fmaxf(fmaxf(sacc[0][0], sacc[0][1]), fmaxf(sacc[1][0], sacc[1][1]));
        float ml_g8 = fmaxf(fmaxf(sacc[0][2], sacc[0][3]), fmaxf(sacc[1][2], sacc[1][3]));
        ml_g  = fmaxf(ml_g,  __shfl_xor_sync(0xffffffffu, ml_g, 1));
        ml_g  = fmaxf(ml_g,  __shfl_xor_sync(0xffffffffu, ml_g, 2));
        ml_g8 = fmaxf(ml_g8, __shfl_xor_sync(0xffffffffu, ml_g8, 1));
        ml_g8 = fmaxf(ml_g8, __shfl_xor_sync(0xffffffffu, ml_g8, 2));
        float mn_g  = fmaxf(m_g, ml_g),   cor_g  = __expf(m_g - mn_g);
        float mn_g8 = fmaxf(m_g8, ml_g8), cor_g8 = __expf(m_g8 - mn_g8);
        m_g = mn_g; m_g8 = mn_g8;

        float pp[2][4];
        float ls_g = 0.0f, ls_g8 = 0.0f;
#pragma unroll
        for (int nb = 0; nb < 2; ++nb) {
            pp[nb][0] = __expf(sacc[nb][0] - mn_g);
            pp[nb][1] = __expf(sacc[nb][1] - mn_g);
            pp[nb][2] = __expf(sacc[nb][2] - mn_g8);
            pp[nb][3] = __expf(sacc[nb][3] - mn_g8);
            ls_g  += pp[nb][0] + pp[nb][1];
            ls_g8 += pp[nb][2] + pp[nb][3];
        }
        ls_g  += __shfl_xor_sync(0xffffffffu, ls_g, 1);
        ls_g  += __shfl_xor_sync(0xffffffffu, ls_g, 2);
        ls_g8 += __shfl_xor_sync(0xffffffffu, ls_g8, 1);
        ls_g8 += __shfl_xor_sync(0xffffffffu, ls_g8, 2);
        l_g  = l_g  * cor_g  + ls_g;
        l_g8 = l_g8 * cor_g8 + ls_g8;

#pragma unroll
        for (int nb = 0; nb < 4; ++nb) {
            oacc[nb][0] *= cor_g;  oacc[nb][1] *= cor_g;
            oacc[nb][2] *= cor_g8; oacc[nb][3] *= cor_g8;
        }

        // ---- C-frag -> A-frag via quad shuffles, then PV ----
        uint32_t pt[2][4];
#pragma unroll
        for (int nb = 0; nb < 2; ++nb)
#pragma unroll
            for (int e = 0; e < 4; ++e) pt[nb][e] = to_tf32(pp[nb][e]);

#pragma unroll
        for (int kc = 0; kc < 2; ++kc) {
            uint32_t v0 = __shfl_sync(0xffffffffu, pt[kc][0], srcA);
            uint32_t v1 = __shfl_sync(0xffffffffu, pt[kc][1], srcA);
            uint32_t w0 = __shfl_sync(0xffffffffu, pt[kc][2], srcA);
            uint32_t w1 = __shfl_sync(0xffffffffu, pt[kc][3], srcA);
            uint32_t x0 = __shfl_sync(0xffffffffu, pt[kc][0], srcC);
            uint32_t x1 = __shfl_sync(0xffffffffu, pt[kc][1], srcC);
            uint32_t y0 = __shfl_sync(0xffffffffu, pt[kc][2], srcC);
            uint32_t y1 = __shfl_sync(0xffffffffu, pt[kc][3], srcC);
            uint32_t a0 = (q & 1) ? v1 : v0;
            uint32_t a1 = (q & 1) ? w1 : w0;
            uint32_t a2 = (q & 1) ? x1 : x0;
            uint32_t a3 = (q & 1) ? y1 : y0;
#pragma unroll
            for (int nbd = 0; nbd < 4; ++nbd) {
                uint32_t b0 = uV[(kc * 8 + q) * 264 + (h << 5) + nbd * 8 + g];
                uint32_t b1 = uV[(kc * 8 + q + 4) * 264 + (h << 5) + nbd * 8 + g];
                mma_tf32(oacc[nbd], a0, a1, a2, a3, b0, b1);
            }
        }

        __syncthreads();
        if (i + 2 < n) fill(i + 2, sp);
    }

    // ---- normalize, write O (tf32 bits) into this tile's q-slot -------------
    {
        float inv_g = 1.0f / l_g, inv_g8 = 1.0f / l_g8;
#pragma unroll
        for (int nbd = 0; nbd < 4; ++nbd) {
            int c0 = (h << 5) + nbd * 8 + 2 * q;
            u64 w0 = (u64)to_tf32(oacc[nbd][0] * inv_g)
                   | ((u64)to_tf32(oacc[nbd][1] * inv_g) << 32);
            u64 w1 = (u64)to_tf32(oacc[nbd][2] * inv_g8)
                   | ((u64)to_tf32(oacc[nbd][3] * inv_g8) << 32);
            *(u64*)&tbu[g * 768 + c0]       = w0;
            *(u64*)&tbu[(g + 8) * 768 + c0] = w1;
        }
    }
}

// ---------------- K4: output projection, 4 hb-consecutive tiles per CTA ------
// The 4 tiles share (b, vb) with hb = hg*4..hg*4+3 -> together they cover 16
// consecutive ww columns. Results staged through smem [c][py][16 ww] and
// stored as float4 -> fully-coalesced 64B segments (8x less write traffic).
__global__ __launch_bounds__(256, 3) void outproj_mma_kernel(const float* __restrict__ b_out,
                                                             float* __restrict__ out) {
    extern __shared__ uint32_t sO[];    // 4 x 4160 = 16640 words (66560 B)

    const int t = threadIdx.x;
    const int warp = t >> 5, lane = t & 31;
    const int g = lane >> 2, q = lane & 3;
    const int nblk = blockIdx.x;            // 0..2047
    const int b  = nblk >> 10;
    const int hg = (nblk >> 6) & 15;
    const int vb = nblk & 63;

    const uint32_t aO = (uint32_t)__cvta_generic_to_shared(sO);
#pragma unroll
    for (int r = 0; r < 16; ++r) {
        int flat = r * 1024 + t * 4;            // 0..16383
        int tile = flat >> 12;
        int rem = flat & 4095;
        int row = rem >> 8, ch = rem & 255;
        int bid = b * 4096 + (hg * 4 + tile) * 64 + vb;
        const float* src = g_proj + (size_t)bid * 12288 + row * 768 + ch;
        cpa16(aO + (tile * 4160 + row * 260 + ch) * 4, src);
    }
    cp_commit();
    cp_wait<0>();
    __syncthreads();

    float cacc[2][4][4];                        // [cbi][tile][e]
#pragma unroll
    for (int cb = 0; cb < 2; ++cb)
#pragma unroll
        for (int tt = 0; tt < 4; ++tt)
#pragma unroll
            for (int e = 0; e < 4; ++e) cacc[cb][tt][e] = 0.0f;

#pragma unroll 4
    for (int kc = 0; kc < 32; ++kc) {
        u64 w2a = g_wofrag[(((warp * 2 + 0) << 5) + kc) * 32 + lane];
        u64 w2b = g_wofrag[(((warp * 2 + 1) << 5) + kc) * 32 + lane];
        uint32_t ba0 = (uint32_t)(w2a & 0xffffffffu), ba1 = (uint32_t)(w2a >> 32);
        uint32_t bb0 = (uint32_t)(w2b & 0xffffffffu), bb1 = (uint32_t)(w2b >> 32);
#pragma unroll
        for (int tt = 0; tt < 4; ++tt) {
            const uint32_t* uO = sO + tt * 4160;
            uint32_t a0 = uO[g * 260 + kc * 8 + q];
            uint32_t a1 = uO[(g + 8) * 260 + kc * 8 + q];
            uint32_t a2 = uO[g * 260 + kc * 8 + q + 4];
            uint32_t a3 = uO[(g + 8) * 260 + kc * 8 + q + 4];
            mma_tf32(cacc[0][tt], a0, a1, a2, a3, ba0, ba1);
            mma_tf32(cacc[1][tt], a0, a1, a2, a3, bb0, bb1);
        }
    }
    __syncthreads();                            // sO reads done; reuse as stash

    // ---- stash results: st[(c*4 + py)*16 + tt*4 + px], bias added ----
    float* st = (float*)sO;                     // 8192 floats = 32KB
    const int pxg = g >> 2, pyg = g & 3;        // rows g: px 0..1; g+8: px+2
#pragma unroll
    for (int cbi = 0; cbi < 2; ++cbi) {
#pragma unroll
        for (int e = 0; e < 2; ++e) {
            int c = (warp * 2 + cbi) * 8 + 2 * q + e;
            float bo = __ldg(&b_out[c]);
            int rowbase = (c * 4 + pyg) * 16;
#pragma unroll
            for (int tt = 0; tt < 4; ++tt) {
                st[rowbase + tt * 4 + pxg]     = cacc[cbi][tt][e] + bo;
                st[rowbase + tt * 4 + pxg + 2] = cacc[cbi][tt][e + 2] + bo;
            }
        }
    }
    __syncthreads();

    // ---- coalesced store: each float4 covers 16B of a 64B (c,py) row ----
    const size_t ob = ((size_t)b << 23) + (size_t)(vb * 4) * 256 + hg * 16;
#pragma unroll
    for (int i = 0; i < 8; ++i) {
        int flat = i * 1024 + t * 4;            // 0..8191, 16B aligned
        int row = flat >> 4, col = flat & 15;
        int c = row >> 2, py = row & 3;
        float4 v = *(const float4*)&st[flat];
        *(float4*)&out[ob + (size_t)c * 65536 + py * 256 + col] = v;
    }
}

// ---------------------------------------------------------------------------
extern "C" void kernel_launch(void* const* d_in, const int* in_sizes, int n_in,
                              void* d_out, int out_size) {
    (void)in_sizes; (void)n_in; (void)out_size;
    const float* x     = (const float*)d_in[0];
    const float* w_in  = (const float*)d_in[1];
    const float* b_in  = (const float*)d_in[2];
    const float* w_out = (const float*)d_in[3];
    const float* b_out = (const float*)d_in[4];
    float* out = (float*)d_out;

    static int configured = 0;
    if (!configured) {
        cudaFuncSetAttribute(attn_mma_kernel, cudaFuncAttributeMaxDynamicSharedMemorySize, 69632);
        cudaFuncSetAttribute(outproj_mma_kernel, cudaFuncAttributeMaxDynamicSharedMemorySize, 66560);
        configured = 1;
    }

    wfrag_kernel<<<96, 256>>>(w_in);
    wofrag_kernel<<<64, 256>>>(w_out);
    proj_mma_kernel<<<2048, 256>>>(x, b_in);
    attn_mma_kernel<<<8192, 256, 68096>>>();
    outproj_mma_kernel<<<2048, 256, 66560>>>(b_out, out);
}

// round 16
// speedup vs baseline: 2.3500x; 1.0667x over previous
#include <cuda_runtime.h>
#include <cstdint>

// AttentionConvolution2D: B=2, DIN=128, H=W=256, BS=4, NH=8, DH=32, DOUT=128
typedef unsigned long long u64;

__device__ __forceinline__ uint32_t to_tf32(float f) {
    uint32_t r; asm("cvt.rna.tf32.f32 %0, %1;" : "=r"(r) : "f"(f)); return r;
}
__device__ __forceinline__ void mma_tf32(float* d,
                                         uint32_t a0, uint32_t a1, uint32_t a2, uint32_t a3,
                                         uint32_t b0, uint32_t b1) {
    asm("mma.sync.aligned.m16n8k8.row.col.f32.tf32.tf32.f32 "
        "{%0,%1,%2,%3}, {%4,%5,%6,%7}, {%8,%9}, {%0,%1,%2,%3};"
        : "+f"(d[0]), "+f"(d[1]), "+f"(d[2]), "+f"(d[3])
        : "r"(a0), "r"(a1), "r"(a2), "r"(a3), "r"(b0), "r"(b1));
}
__device__ __forceinline__ void cpa16(uint32_t dst, const void* src) {
    asm volatile("cp.async.cg.shared.global [%0], [%1], 16;" :: "r"(dst), "l"(src));
}
__device__ __forceinline__ void cp_commit() {
    asm volatile("cp.async.commit_group;");
}
template <int N> __device__ __forceinline__ void cp_wait() {
    asm volatile("cp.async.wait_group %0;" :: "n"(N));
}

// proj scratch, tile-major, TF32 BIT PATTERNS (q pre-scaled by 1/sqrt(32)):
// tile=(b*64+hb)*64+vb, row=pixel pi=(w&3)*4+(h&3), 768 ch/row (q|k|v)
// q and k regions use PERMUTED channel order within each 8-group:
//   pos(c) = 2*(c&3) + (c>>2)  -> fragment cols (q, q+4) land adjacent.
// v region is in natural order.
// After attn, the q slot of each tile holds that tile's normalized O (tf32,
// standard fragment layout).
__device__ float g_proj[100663296];     // 131072*768 words
__device__ uint32_t g_wfrag[98304];     // w_in  in m16n8k8 A-fragment order (tf32)
__device__ u64 g_wofrag[16384];         // w_out in m16n8k8 B-fragment order (tf32 pairs)

// ---------------- K1a: pack w_in (768x128) into A-fragment order -------------
__global__ void wfrag_kernel(const float* __restrict__ w_in) {
    int idx = blockIdx.x * 256 + threadIdx.x;     // 0..24575
    if (idx >= 24576) return;
    int lane = idx & 31, kk = (idx >> 5) & 15, mb = idx >> 9;
    int g = lane >> 2, q = lane & 3;
    int r0 = mb * 16 + g, r1 = r0 + 8;
    int c0 = kk * 8 + q,  c1 = c0 + 4;
    uint4 o;
    o.x = to_tf32(w_in[r0 * 128 + c0]);
    o.y = to_tf32(w_in[r1 * 128 + c0]);
    o.z = to_tf32(w_in[r0 * 128 + c1]);
    o.w = to_tf32(w_in[r1 * 128 + c1]);
    *(uint4*)&g_wfrag[idx * 4] = o;
}

// ---------------- K1b: pack w_out (128x256) into B-fragment order ------------
__global__ void wofrag_kernel(const float* __restrict__ w_out) {
    int f = blockIdx.x * 256 + threadIdx.x;       // 0..16383
    if (f >= 16384) return;
    int lane = f & 31, kc = (f >> 5) & 31, cb = f >> 10;
    int g = lane >> 2, q = lane & 3;
    int c = cb * 8 + g;
    uint32_t b0 = to_tf32(w_out[c * 256 + kc * 8 + q]);
    uint32_t b1 = to_tf32(w_out[c * 256 + kc * 8 + q + 4]);
    g_wofrag[f] = (u64)b0 | ((u64)b1 << 32);
}

// ---------------- K2: projection GEMM via tf32 MMA ---------------------------
// Epilogue permutes q/k-region channel positions within 8-groups.
__global__ __launch_bounds__(256) void proj_mma_kernel(const float* __restrict__ x,
                                                       const float* __restrict__ b_in) {
    __shared__ uint32_t sB[128 * 72];   // 36864 B

    const int t   = threadIdx.x;
    const int pbk = blockIdx.x;           // 0..2047
    const int b   = pbk >> 10;
    const int rem = pbk & 1023;
    const int hc  = rem >> 2;             // h 0..255
    const int w0  = (rem & 3) << 6;       // first w of strip

    const float* xb = x + ((size_t)b << 23) + (size_t)hc * 256 + w0;

#pragma unroll
    for (int r = 0; r < 8; ++r) {
        int flat = r * 1024 + t * 4;
        int k = flat >> 6, px = flat & 63;
        float4 v = *(const float4*)&xb[(size_t)k * 65536 + px];
        uint4 o = { to_tf32(v.x), to_tf32(v.y), to_tf32(v.z), to_tf32(v.w) };
        *(uint4*)&sB[k * 72 + px] = o;
    }
    __syncthreads();

    const int warp = t >> 5, lane = t & 31;
    const int wm = warp >> 1, wn = warp & 1;
    const int nw0 = wn << 5;
    const int g = lane >> 2, q = lane & 3;
    const int gperm = 2 * (g & 3) + (g >> 2);   // permuted in-group position

    const int vbb = hc >> 2, py = hc & 3;
    size_t pxbase[4][2];
#pragma unroll
    for (int nb = 0; nb < 4; ++nb)
#pragma unroll
        for (int e = 0; e < 2; ++e) {
            int i  = nw0 + nb * 8 + 2 * q + e;
            int w  = w0 + i;
            int hb = w >> 2, pxm = w & 3;
            pxbase[nb][e] = ((((size_t)b * 64 + hb) * 64 + vbb) * 16 + pxm * 4 + py) * 768;
        }

    const float SCALE = 0.17677669529663687f;   // 1/sqrt(32)

    for (int nbk = 0; nbk < 6; ++nbk) {
        const int mbase = nbk * 8 + wm * 2;
        const float sc = (nbk < 2) ? SCALE : 1.0f;
        const int gp = (nbk < 4) ? gperm : g;   // permute q|k regions only
        float acc[2][4][4];
#pragma unroll
        for (int m = 0; m < 2; ++m)
#pragma unroll
            for (int nb = 0; nb < 4; ++nb)
#pragma unroll
                for (int e = 0; e < 4; ++e) acc[m][nb][e] = 0.0f;

#pragma unroll
        for (int kk = 0; kk < 16; ++kk) {
            uint4 a0 = *(const uint4*)&g_wfrag[(((mbase + 0) * 16 + kk) * 32 + lane) * 4];
            uint4 a1 = *(const uint4*)&g_wfrag[(((mbase + 1) * 16 + kk) * 32 + lane) * 4];
            const int rb0 = (kk * 8 + q) * 72 + nw0 + g;
#pragma unroll
            for (int nb = 0; nb < 4; ++nb) {
                uint32_t bf0 = sB[rb0 + nb * 8];
                uint32_t bf1 = sB[rb0 + 288 + nb * 8];
                mma_tf32(acc[0][nb], a0.x, a0.y, a0.z, a0.w, bf0, bf1);
                mma_tf32(acc[1][nb], a1.x, a1.y, a1.z, a1.w, bf0, bf1);
            }
        }

#pragma unroll
        for (int m = 0; m < 2; ++m) {
            int b16  = nbk * 128 + (wm * 2 + m) * 16;
            float bias0 = b_in[b16 + g];        // bias by LOGICAL channel
            float bias1 = b_in[b16 + 8 + g];
            int chS = b16 + gp;                 // permuted store position
#pragma unroll
            for (int nb = 0; nb < 4; ++nb) {
                g_proj[pxbase[nb][0] + chS]     = __uint_as_float(to_tf32((acc[m][nb][0] + bias0) * sc));
                g_proj[pxbase[nb][1] + chS]     = __uint_as_float(to_tf32((acc[m][nb][1] + bias0) * sc));
                g_proj[pxbase[nb][0] + chS + 8] = __uint_as_float(to_tf32((acc[m][nb][2] + bias1) * sc));
                g_proj[pxbase[nb][1] + chS + 8] = __uint_as_float(to_tf32((acc[m][nb][3] + bias1) * sc));
            }
        }
    }
}

// ---------------- K3: attention mainloop, O -> g_proj q-slot -----------------
// Stage: K 16x264 | V 16x264 = 8448 words; two stages = 67584 B.
#define STAGE_WORDS 8448

__global__ __launch_bounds__(256, 3) void attn_mma_kernel() {
    extern __shared__ uint32_t usm[];

    const int bid = blockIdx.x;
    const int vb = bid & 63;
    const int hb = (bid >> 6) & 63;
    const int b  = bid >> 12;
    const int t  = threadIdx.x;
    const int warp = t >> 5, lane = t & 31;
    const int h = warp;
    const int g = lane >> 2, q = lane & 3;

    uint32_t* tbu = (uint32_t*)g_proj + (size_t)bid * 12288;

    // ---- Q fragments (permuted layout -> 64-bit pair loads) ----
    uint32_t qa0[4], qa1[4], qa2[4], qa3[4];
#pragma unroll
    for (int kc = 0; kc < 4; ++kc) {
        int base = (h << 5) + kc * 8 + 2 * q;
        uint2 vg  = *(const uint2*)&tbu[g * 768 + base];
        uint2 vg8 = *(const uint2*)&tbu[(g + 8) * 768 + base];
        qa0[kc] = vg.x;  qa2[kc] = vg.y;
        qa1[kc] = vg8.x; qa3[kc] = vg8.y;
    }

    // ---- valid neighbor list ----
    int nidx[9], ndxy[9], n = 0;
    for (int dx = 0; dx < 3; ++dx) {
        int nhb = hb + dx - 1;
        if ((unsigned)nhb >= 64u) continue;      // boundary == -inf mask
        for (int dy = 0; dy < 3; ++dy) {
            int nvb = vb + dy - 1;
            if ((unsigned)nvb >= 64u) continue;
            nidx[n] = (b << 12) + (nhb << 6) + nvb;
            ndxy[n] = (dx << 4) | dy;
            ++n;
        }
    }

    const uint32_t aS = (uint32_t)__cvta_generic_to_shared(usm);

    auto fill = [&](int i, int sp) {
        const float* nb_ = g_proj + (size_t)nidx[i] * 12288 + 256;
        uint32_t bs = aS + sp * (STAGE_WORDS * 4);
#pragma unroll
        for (int r = 0; r < 4; ++r) {
            int flat = r * 1024 + t * 4;
            int key = flat >> 8, ch = flat & 255;
            cpa16(bs + (key * 264 + ch) * 4, nb_ + key * 768 + ch);
            cpa16(bs + (4224 + key * 264 + ch) * 4, nb_ + key * 768 + 256 + ch);
        }
        cp_commit();
    };

    float oacc[4][4];
#pragma unroll
    for (int nb = 0; nb < 4; ++nb)
#pragma unroll
        for (int e = 0; e < 4; ++e) oacc[nb][e] = 0.0f;
    float m_g = -1e30f, m_g8 = -1e30f, l_g = 0.0f, l_g8 = 0.0f;

    // float bias bases (exact small-int floats)
    const float fqx_g  = (float)(g >> 2),       fqy_g  = (float)(g & 3);
    const float fqx_g8 = (float)((g + 8) >> 2), fqy_g8 = (float)((g + 8) & 3);
    const int srcA = (lane & 0x1c) | (q >> 1);
    const int srcC = srcA + 2;

    fill(0, 0);
    if (n > 1) fill(1, 1);

    for (int i = 0; i < n; ++i) {
        const int sp = i & 1;
        if (i + 1 < n) cp_wait<1>(); else cp_wait<0>();
        __syncthreads();

        const uint32_t* uK = usm + sp * STAGE_WORDS;
        const uint32_t* uV = uK + 4224;
        const int dx = ndxy[i] >> 4, dy = ndxy[i] & 15;

        // ---- QK (K permuted -> LDS.64 pairs) ----
        float sacc[2][4];
#pragma unroll
        for (int nb = 0; nb < 2; ++nb)
#pragma unroll
            for (int e = 0; e < 4; ++e) sacc[nb][e] = 0.0f;
#pragma unroll
        for (int kc = 0; kc < 4; ++kc) {
#pragma unroll
            for (int nb = 0; nb < 2; ++nb) {
                uint2 kv = *(const uint2*)&uK[(nb * 8 + g) * 264 + (h << 5) + kc * 8 + 2 * q];
                mma_tf32(sacc[nb], qa0[kc], qa1[kc], qa2[kc], qa3[kc], kv.x, kv.y);
            }
        }

        // ---- bias via fma pipe (bit-identical: *0.0625 is exact) ----
        const float fdx4 = (float)(dx * 4), fdy4 = (float)(dy * 4);
        const float bxg = fdx4 - fqx_g - 4.0f,  byg = fdy4 - fqy_g - 4.0f;
        const float bxh = fdx4 - fqx_g8 - 4.0f, byh = fdy4 - fqy_g8 - 4.0f;
#pragma unroll
        for (int nb = 0; nb < 2; ++nb)
#pragma unroll
            for (int e = 0; e < 2; ++e) {
                int j = nb * 8 + 2 * q + e;
                float fjx = (float)(j >> 2), fjy = (float)(j & 3);
                float ixg = bxg + fjx, iyg = byg + fjy;
                float ixh = bxh + fjx, iyh = byh + fjy;
                float tg = fmaf(ixg, ixg, iyg * iyg);
                float th = fmaf(ixh, ixh, iyh * iyh);
                sacc[nb][e]     = fmaf(tg, -0.0625f, sacc[nb][e]);
                sacc[nb][e + 2] = fmaf(th, -0.0625f, sacc[nb][e + 2]);
            }

        // ---- online softmax (rows g, g+8) ----
        float ml_g  = fmaxf(fmaxf(sacc[0][0], sacc[0][1]), fmaxf(sacc[1][0], sacc[1][1]));
        float ml_g8 = fmaxf(fmaxf(sacc[0][2], sacc[0][3]), fmaxf(sacc[1][2], sacc[1][3]));
        ml_g  = fmaxf(ml_g,  __shfl_xor_sync(0xffffffffu, ml_g, 1));
        ml_g  = fmaxf(ml_g,  __shfl_xor_sync(0xffffffffu, ml_g, 2));
        ml_g8 = fmaxf(ml_g8, __shfl_xor_sync(0xffffffffu, ml_g8, 1));
        ml_g8 = fmaxf(ml_g8, __shfl_xor_sync(0xffffffffu, ml_g8, 2));
        float mn_g  = fmaxf(m_g, ml_g),   cor_g  = __expf(m_g - mn_g);
        float mn_g8 = fmaxf(m_g8, ml_g8), cor_g8 = __expf(m_g8 - mn_g8);
        m_g = mn_g; m_g8 = mn_g8;

        float pp[2][4];
        float ls_g = 0.0f, ls_g8 = 0.0f;
#pragma unroll
        for (int nb = 0; nb < 2; ++nb) {
            pp[nb][0] = __expf(sacc[nb][0] - mn_g);
            pp[nb][1] = __expf(sacc[nb][1] - mn_g);
            pp[nb][2] = __expf(sacc[nb][2] - mn_g8);
            pp[nb][3] = __expf(sacc[nb][3] - mn_g8);
            ls_g  += pp[nb][0] + pp[nb][1];
            ls_g8 += pp[nb][2] + pp[nb][3];
        }
        ls_g  += __shfl_xor_sync(0xffffffffu, ls_g, 1);
        ls_g  += __shfl_xor_sync(0xffffffffu, ls_g, 2);
        ls_g8 += __shfl_xor_sync(0xffffffffu, ls_g8, 1);
        ls_g8 += __shfl_xor_sync(0xffffffffu, ls_g8, 2);
        l_g  = l_g  * cor_g  + ls_g;
        l_g8 = l_g8 * cor_g8 + ls_g8;

#pragma unroll
        for (int nb = 0; nb < 4; ++nb) {
            oacc[nb][0] *= cor_g;  oacc[nb][1] *= cor_g;
            oacc[nb][2] *= cor_g8; oacc[nb][3] *= cor_g8;
        }

        // ---- C-frag -> A-frag via quad shuffles, then PV ----
        uint32_t pt[2][4];
#pragma unroll
        for (int nb = 0; nb < 2; ++nb)
#pragma unroll
            for (int e = 0; e < 4; ++e) pt[nb][e] = to_tf32(pp[nb][e]);

#pragma unroll
        for (int kc = 0; kc < 2; ++kc) {
            uint32_t v0 = __shfl_sync(0xffffffffu, pt[kc][0], srcA);
            uint32_t v1 = __shfl_sync(0xffffffffu, pt[kc][1], srcA);
            uint32_t w0 = __shfl_sync(0xffffffffu, pt[kc][2], srcA);
            uint32_t w1 = __shfl_sync(0xffffffffu, pt[kc][3], srcA);
            uint32_t x0 = __shfl_sync(0xffffffffu, pt[kc][0], srcC);
            uint32_t x1 = __shfl_sync(0xffffffffu, pt[kc][1], srcC);
            uint32_t y0 = __shfl_sync(0xffffffffu, pt[kc][2], srcC);
            uint32_t y1 = __shfl_sync(0xffffffffu, pt[kc][3], srcC);
            uint32_t a0 = (q & 1) ? v1 : v0;
            uint32_t a1 = (q & 1) ? w1 : w0;
            uint32_t a2 = (q & 1) ? x1 : x0;
            uint32_t a3 = (q & 1) ? y1 : y0;
#pragma unroll
            for (int nbd = 0; nbd < 4; ++nbd) {
                uint32_t b0 = uV[(kc * 8 + q) * 264 + (h << 5) + nbd * 8 + g];
                uint32_t b1 = uV[(kc * 8 + q + 4) * 264 + (h << 5) + nbd * 8 + g];
                mma_tf32(oacc[nbd], a0, a1, a2, a3, b0, b1);
            }
        }

        __syncthreads();
        if (i + 2 < n) fill(i + 2, sp);
    }

    // ---- normalize, write O (tf32 bits, standard layout) into q-slot --------
    {
        float inv_g = 1.0f / l_g, inv_g8 = 1.0f / l_g8;
#pragma unroll
        for (int nbd = 0; nbd < 4; ++nbd) {
            int c0 = (h << 5) + nbd * 8 + 2 * q;
            u64 w0 = (u64)to_tf32(oacc[nbd][0] * inv_g)
                   | ((u64)to_tf32(oacc[nbd][1] * inv_g) << 32);
            u64 w1 = (u64)to_tf32(oacc[nbd][2] * inv_g8)
                   | ((u64)to_tf32(oacc[nbd][3] * inv_g8) << 32);
            *(u64*)&tbu[g * 768 + c0]       = w0;
            *(u64*)&tbu[(g + 8) * 768 + c0] = w1;
        }
    }
}

// ---------------- K4: output projection, 4 hb-consecutive tiles per CTA ------
__global__ __launch_bounds__(256, 3) void outproj_mma_kernel(const float* __restrict__ b_out,
                                                             float* __restrict__ out) {
    extern __shared__ uint32_t sO[];    // 4 x 4160 = 16640 words (66560 B)

    const int t = threadIdx.x;
    const int warp = t >> 5, lane = t & 31;
    const int g = lane >> 2, q = lane & 3;
    const int nblk = blockIdx.x;            // 0..2047
    const int b  = nblk >> 10;
    const int hg = (nblk >> 6) & 15;
    const int vb = nblk & 63;

    const uint32_t aO = (uint32_t)__cvta_generic_to_shared(sO);
#pragma unroll
    for (int r = 0; r < 16; ++r) {
        int flat = r * 1024 + t * 4;            // 0..16383
        int tile = flat >> 12;
        int rem = flat & 4095;
        int row = rem >> 8, ch = rem & 255;
        int bid = b * 4096 + (hg * 4 + tile) * 64 + vb;
        const float* src = g_proj + (size_t)bid * 12288 + row * 768 + ch;
        cpa16(aO + (tile * 4160 + row * 260 + ch) * 4, src);
    }
    cp_commit();
    cp_wait<0>();
    __syncthreads();

    float cacc[2][4][4];                        // [cbi][tile][e]
#pragma unroll
    for (int cb = 0; cb < 2; ++cb)
#pragma unroll
        for (int tt = 0; tt < 4; ++tt)
#pragma unroll
            for (int e = 0; e < 4; ++e) cacc[cb][tt][e] = 0.0f;

#pragma unroll 4
    for (int kc = 0; kc < 32; ++kc) {
        u64 w2a = g_wofrag[(((warp * 2 + 0) << 5) + kc) * 32 + lane];
        u64 w2b = g_wofrag[(((warp * 2 + 1) << 5) + kc) * 32 + lane];
        uint32_t ba0 = (uint32_t)(w2a & 0xffffffffu), ba1 = (uint32_t)(w2a >> 32);
        uint32_t bb0 = (uint32_t)(w2b & 0xffffffffu), bb1 = (uint32_t)(w2b >> 32);
#pragma unroll
        for (int tt = 0; tt < 4; ++tt) {
            const uint32_t* uO = sO + tt * 4160;
            uint32_t a0 = uO[g * 260 + kc * 8 + q];
            uint32_t a1 = uO[(g + 8) * 260 + kc * 8 + q];
            uint32_t a2 = uO[g * 260 + kc * 8 + q + 4];
            uint32_t a3 = uO[(g + 8) * 260 + kc * 8 + q + 4];
            mma_tf32(cacc[0][tt], a0, a1, a2, a3, ba0, ba1);
            mma_tf32(cacc[1][tt], a0, a1, a2, a3, bb0, bb1);
        }
    }
    __syncthreads();                            // sO reads done; reuse as stash

    // ---- stash results: st[(c*4 + py)*16 + tt*4 + px], bias added ----
    float* st = (float*)sO;                     // 8192 floats = 32KB
    const int pxg = g >> 2, pyg = g & 3;
#pragma unroll
    for (int cbi = 0; cbi < 2; ++cbi) {
#pragma unroll
        for (int e = 0; e < 2; ++e) {
            int c = (warp * 2 + cbi) * 8 + 2 * q + e;
            float bo = __ldg(&b_out[c]);
            int rowbase = (c * 4 + pyg) * 16;
#pragma unroll
            for (int tt = 0; tt < 4; ++tt) {
                st[rowbase + tt * 4 + pxg]     = cacc[cbi][tt][e] + bo;
                st[rowbase + tt * 4 + pxg + 2] = cacc[cbi][tt][e + 2] + bo;
            }
        }
    }
    __syncthreads();

    // ---- coalesced store: each float4 covers 16B of a 64B (c,py) row ----
    const size_t ob = ((size_t)b << 23) + (size_t)(vb * 4) * 256 + hg * 16;
#pragma unroll
    for (int i = 0; i < 8; ++i) {
        int flat = i * 1024 + t * 4;            // 0..8191, 16B aligned
        int row = flat >> 4, col = flat & 15;
        int c = row >> 2, py = row & 3;
        float4 v = *(const float4*)&st[flat];
        *(float4*)&out[ob + (size_t)c * 65536 + py * 256 + col] = v;
    }
}

// ---------------------------------------------------------------------------
extern "C" void kernel_launch(void* const* d_in, const int* in_sizes, int n_in,
                              void* d_out, int out_size) {
    (void)in_sizes; (void)n_in; (void)out_size;
    const float* x     = (const float*)d_in[0];
    const float* w_in  = (const float*)d_in[1];
    const float* b_in  = (const float*)d_in[2];
    const float* w_out = (const float*)d_in[3];
    const float* b_out = (const float*)d_in[4];
    float* out = (float*)d_out;

    static int configured = 0;
    if (!configured) {
        cudaFuncSetAttribute(attn_mma_kernel, cudaFuncAttributeMaxDynamicSharedMemorySize, 69632);
        cudaFuncSetAttribute(outproj_mma_kernel, cudaFuncAttributeMaxDynamicSharedMemorySize, 66560);
        configured = 1;
    }

    wfrag_kernel<<<96, 256>>>(w_in);
    wofrag_kernel<<<64, 256>>>(w_out);
    proj_mma_kernel<<<2048, 256>>>(x, b_in);
    attn_mma_kernel<<<8192, 256, 67584>>>();
    outproj_mma_kernel<<<2048, 256, 66560>>>(b_out, out);
}